// round 6
// baseline (speedup 1.0000x reference)
#include <cuda_runtime.h>
#include <cuda_bf16.h>
#include <cstdint>

#define D_  2048
#define H_  1408
#define HS_ 2816
#define E_  8
#define N_  4096
#define NK_ (2*N_)

constexpr size_t EDH = (size_t)E_ * D_ * H_;
constexpr size_t DHS = (size_t)D_ * HS_;
constexpr size_t XSZ = (size_t)N_ * D_;
constexpr size_t HBUFSZ = 11534336;  // max(4096*2816, 8192*1408)

// -------- static scratch (no runtime allocation anywhere) --------
__device__ __align__(16) int8_t g_qwg1[EDH], g_qwg2[EDH];   // [E][H][D]
__device__ __align__(16) int8_t g_qwu1[EDH], g_qwu2[EDH];   // [E][H][D]
__device__ __align__(16) int8_t g_qwd1[EDH], g_qwd2[EDH];   // [E][D][H]
__device__ __align__(16) int8_t g_qsg1[DHS], g_qsg2[DHS];   // [HS][D]
__device__ __align__(16) int8_t g_qsu1[DHS], g_qsu2[DHS];   // [HS][D]
__device__ __align__(16) int8_t g_qsd1[DHS], g_qsd2[DHS];   // [D][HS]
__device__ __align__(16) int8_t g_qx1[XSZ], g_qx2[XSZ];     // [N][D]
__device__ __align__(16) int8_t g_qh1[HBUFSZ], g_qh2[HBUFSZ];
__device__ float g_hf[HBUFSZ];       // fp32 hidden activations
__device__ float g_mwg[E_ * H_], g_mwu[E_ * H_], g_mwd[E_ * D_];   // col maxima
__device__ float g_msg[HS_], g_msu[HS_], g_msd[D_];
__device__ float g_sx[N_];           // per-token x scale (s1)
__device__ float g_sh[NK_];          // per-row h scale (s1)
__device__ int   g_perm[NK_];
__device__ float g_pgate[NK_];
__device__ int   g_counts[E_];
__device__ int   g_offsets[E_ + 1];
__device__ int   g_gidx[NK_];
__device__ float g_gval[NK_];

// -------- helpers --------
__device__ __forceinline__ void cpa(uint32_t d, const void* s) {
    asm volatile("cp.async.cg.shared.global [%0], [%1], 16;" :: "r"(d), "l"(s));
}
__device__ __forceinline__ void ldmx4(uint32_t* r, uint32_t a) {
    asm volatile("ldmatrix.sync.aligned.m8n8.x4.shared.b16 {%0,%1,%2,%3}, [%4];"
                 : "=r"(r[0]), "=r"(r[1]), "=r"(r[2]), "=r"(r[3]) : "r"(a));
}
__device__ __forceinline__ void imma(int* c, const uint32_t* a, const uint32_t* b) {
    asm volatile(
        "mma.sync.aligned.m16n8k32.row.col.s32.s8.s8.s32 "
        "{%0,%1,%2,%3},{%4,%5,%6,%7},{%8,%9},{%0,%1,%2,%3};"
        : "+r"(c[0]), "+r"(c[1]), "+r"(c[2]), "+r"(c[3])
        : "r"(a[0]), "r"(a[1]), "r"(a[2]), "r"(a[3]), "r"(b[0]), "r"(b[1]));
}
__device__ __forceinline__ void quant2(float v, float s1, float inv, int8_t& o1, int8_t& o2) {
    float a1 = rintf(v * inv);
    a1 = fminf(fmaxf(a1, -127.f), 127.f);
    float r = v - s1 * a1;
    float a2 = rintf(r * inv * 254.f);
    a2 = fminf(fmaxf(a2, -127.f), 127.f);
    o1 = (int8_t)a1; o2 = (int8_t)a2;
}

// -------- weight column-max (per output feature over K) --------
__global__ void wmaxcol(const float* __restrict__ src, float* __restrict__ mx,
                        int R, int C) {
    __shared__ float t[32][33];
    size_t zo = (size_t)blockIdx.z * R * C;
    src += zo;
    int c0 = blockIdx.x * 32, r0 = blockIdx.y * 32;
    int tx = threadIdx.x, ty = threadIdx.y;
#pragma unroll
    for (int i = 0; i < 4; i++)
        t[ty + 8 * i][tx] = fabsf(src[(size_t)(r0 + ty + 8 * i) * C + c0 + tx]);
    __syncthreads();
    float m = fmaxf(fmaxf(t[ty][tx], t[ty + 8][tx]),
                    fmaxf(t[ty + 16][tx], t[ty + 24][tx]));
    __syncthreads();
    t[ty][tx] = m;
    __syncthreads();
    if (ty == 0) {
        float mm = t[0][tx];
#pragma unroll
        for (int r = 1; r < 8; r++) mm = fmaxf(mm, t[r][tx]);
        atomicMax((unsigned*)&mx[(size_t)blockIdx.z * C + c0 + tx], __float_as_uint(mm));
    }
}

// -------- weight quantize + transpose: [R][C] fp32 -> [C][R] int8 planes --------
__global__ void wquant(const float* __restrict__ src, const float* __restrict__ mx,
                       int8_t* __restrict__ q1, int8_t* __restrict__ q2, int R, int C) {
    __shared__ float t[32][33];
    size_t zo = (size_t)blockIdx.z * R * C;
    src += zo; q1 += zo; q2 += zo;
    const float* mxz = mx + (size_t)blockIdx.z * C;
    int c0 = blockIdx.x * 32, r0 = blockIdx.y * 32;
    int tx = threadIdx.x, ty = threadIdx.y;
#pragma unroll
    for (int i = 0; i < 4; i++)
        t[ty + 8 * i][tx] = src[(size_t)(r0 + ty + 8 * i) * C + c0 + tx];
    __syncthreads();
#pragma unroll
    for (int i = 0; i < 4; i++) {
        int c = c0 + ty + 8 * i;
        float s1 = fmaxf(mxz[c], 1e-20f) * (1.f / 127.f);
        float inv = 1.f / s1;
        float v = t[tx][ty + 8 * i];
        int8_t a, b; quant2(v, s1, inv, a, b);
        size_t o = (size_t)c * R + r0 + tx;
        q1[o] = a; q2[o] = b;
    }
}

// -------- x quantize: per-token row --------
__global__ void xquant(const float* __restrict__ x) {
    int row = blockIdx.x;
    const float* src = x + (size_t)row * D_;
    __shared__ float red[256];
    __shared__ float s_s1;
    int tid = threadIdx.x;
    float m = 0.f;
    for (int i = tid; i < D_; i += 256) m = fmaxf(m, fabsf(src[i]));
    red[tid] = m; __syncthreads();
    for (int s = 128; s > 0; s >>= 1) {
        if (tid < s) red[tid] = fmaxf(red[tid], red[tid + s]);
        __syncthreads();
    }
    if (tid == 0) {
        float s1 = fmaxf(red[0], 1e-20f) * (1.f / 127.f);
        g_sx[row] = s1; s_s1 = s1;
    }
    __syncthreads();
    float s1 = s_s1, inv = 1.f / s1;
    for (int i = tid; i < D_; i += 256) {
        int8_t a, b; quant2(src[i], s1, inv, a, b);
        g_qx1[(size_t)row * D_ + i] = a;
        g_qx2[(size_t)row * D_ + i] = b;
    }
}

// -------- h quantize: per hbuf row --------
__global__ void hquant(int W) {
    int row = blockIdx.x;
    const float* src = g_hf + (size_t)row * W;
    __shared__ float red[256];
    __shared__ float s_s1;
    int tid = threadIdx.x;
    float m = 0.f;
    for (int i = tid; i < W; i += 256) m = fmaxf(m, fabsf(src[i]));
    red[tid] = m; __syncthreads();
    for (int s = 128; s > 0; s >>= 1) {
        if (tid < s) red[tid] = fmaxf(red[tid], red[tid + s]);
        __syncthreads();
    }
    if (tid == 0) {
        float s1 = fmaxf(red[0], 1e-20f) * (1.f / 127.f);
        g_sh[row] = s1; s_s1 = s1;
    }
    __syncthreads();
    float s1 = s_s1, inv = 1.f / s1;
    for (int i = tid; i < W; i += 256) {
        int8_t a, b; quant2(src[i], s1, inv, a, b);
        g_qh1[(size_t)row * W + i] = a;
        g_qh2[(size_t)row * W + i] = b;
    }
}

// -------- router + list build (proven) --------
__global__ void router_kernel(const float* __restrict__ x, const float* __restrict__ rw) {
    int gw = (blockIdx.x * blockDim.x + threadIdx.x) >> 5;
    int lane = threadIdx.x & 31;
    if (gw >= N_) return;
    const float* xr = x + (size_t)gw * D_;
    float acc[E_];
#pragma unroll
    for (int e = 0; e < E_; e++) acc[e] = 0.f;
    for (int d = lane * 4; d < D_; d += 128) {
        float4 xv = *(const float4*)(xr + d);
#pragma unroll
        for (int e = 0; e < E_; e++) {
            float4 wv = *(const float4*)(rw + e * D_ + d);
            acc[e] += xv.x * wv.x + xv.y * wv.y + xv.z * wv.z + xv.w * wv.w;
        }
    }
#pragma unroll
    for (int e = 0; e < E_; e++) {
#pragma unroll
        for (int o = 16; o > 0; o >>= 1)
            acc[e] += __shfl_down_sync(0xffffffffu, acc[e], o);
    }
    if (lane == 0) {
        float mx = acc[0];
#pragma unroll
        for (int e = 1; e < E_; e++) mx = fmaxf(mx, acc[e]);
        float p[E_], s = 0.f;
#pragma unroll
        for (int e = 0; e < E_; e++) { p[e] = expf(acc[e] - mx); s += p[e]; }
        int i1 = 0;
#pragma unroll
        for (int e = 1; e < E_; e++) if (p[e] > p[i1]) i1 = e;
        int i2 = (i1 == 0) ? 1 : 0;
#pragma unroll
        for (int e = 0; e < E_; e++) if (e != i1 && p[e] > p[i2]) i2 = e;
        float g1 = p[i1] / s, g2 = p[i2] / s;
        float den = g1 + g2 + 1e-20f;
        g_gidx[2 * gw]     = i1; g_gval[2 * gw]     = g1 / den;
        g_gidx[2 * gw + 1] = i2; g_gval[2 * gw + 1] = g2 / den;
    }
}

__global__ void build_lists_kernel() {
    __shared__ int scnt[E_];
    __shared__ int soff[E_];
    int wid = threadIdx.x >> 5, lane = threadIdx.x & 31;
    if (wid < E_) {
        int c = 0;
        for (int base = 0; base < NK_; base += 32) {
            int flag = (g_gidx[base + lane] == wid);
            c += __popc(__ballot_sync(0xffffffffu, flag));
        }
        if (lane == 0) scnt[wid] = c;
    }
    __syncthreads();
    if (threadIdx.x == 0) {
        int s = 0;
        for (int e = 0; e < E_; e++) {
            soff[e] = s; g_offsets[e] = s; g_counts[e] = scnt[e]; s += scnt[e];
        }
        g_offsets[E_] = s;
    }
    __syncthreads();
    if (wid < E_) {
        int pos = soff[wid];
        for (int base = 0; base < NK_; base += 32) {
            int t = base + lane;
            int flag = (g_gidx[t] == wid);
            unsigned m = __ballot_sync(0xffffffffu, flag);
            if (flag) {
                int off = __popc(m & ((1u << lane) - 1u));
                g_perm[pos + off]  = t >> 1;
                g_pgate[pos + off] = g_gval[t];
            }
            pos += __popc(m);
        }
    }
}

// ---------------------------------------------------------------------------
// Fused gate/up int8 IMMA GEMM + SiLU -> g_hf (fp32).
// BM=128 BN=64 BK=64, 256 threads (8 warps, 4m x 2n, warp tile 32x32).
// Two-digit int8: acc0 = a1*b1, acc1 = a1*b2 + a2*b1; C = sA*sB*(acc0+acc1/254).
// Stage (80B rows): A1 0 (10240), A2 10240, G1 20480 (5120), G2 25600,
//   U1 30720, U2 35840. Stage stride 40960.
// ---------------------------------------------------------------------------
#define STG_GU 40960
template<bool ROUTED>
__global__ void __launch_bounds__(256)
gateup_imma(int Nn) {
    int e    = ROUTED ? blockIdx.z : 0;
    int M    = ROUTED ? g_counts[e] : N_;
    int base = ROUTED ? g_offsets[e] : 0;
    int m0 = blockIdx.x * 128;
    if (m0 >= M) return;
    int n0 = blockIdx.y * 64;

    size_t eo = ROUTED ? (size_t)e * D_ * H_ : 0;
    const int8_t* G1 = (ROUTED ? g_qwg1 : g_qsg1) + eo;
    const int8_t* G2 = (ROUTED ? g_qwg2 : g_qsg2) + eo;
    const int8_t* U1 = (ROUTED ? g_qwu1 : g_qsu1) + eo;
    const int8_t* U2 = (ROUTED ? g_qwu2 : g_qsu2) + eo;
    const float* mG = ROUTED ? (g_mwg + e * H_) : g_msg;
    const float* mU = ROUTED ? (g_mwu + e * H_) : g_msu;

    extern __shared__ char smem[];
    __shared__ int stok[128];
    int tid = threadIdx.x;
    if (tid < 128) {
        int r = m0 + tid; if (r > M - 1) r = M - 1;
        stok[tid] = ROUTED ? g_perm[base + r] : r;
    }
    __syncthreads();

    int rowA = tid >> 1, kqA = (tid & 1) * 32;
    const int8_t* pA1 = g_qx1 + (size_t)stok[rowA] * D_ + kqA;
    const int8_t* pA2 = g_qx2 + (size_t)stok[rowA] * D_ + kqA;
    int rowB = tid >> 2, kqB = (tid & 3) * 16;
    const int8_t* pG1 = G1 + (size_t)(n0 + rowB) * D_ + kqB;
    const int8_t* pG2 = G2 + (size_t)(n0 + rowB) * D_ + kqB;
    const int8_t* pU1 = U1 + (size_t)(n0 + rowB) * D_ + kqB;
    const int8_t* pU2 = U2 + (size_t)(n0 + rowB) * D_ + kqB;

    uint32_t sb = (uint32_t)__cvta_generic_to_shared(smem);
    uint32_t dA = sb + rowA * 80 + kqA;
    uint32_t dB = sb + rowB * 80 + kqB;

    auto issue = [&](int stage, int kt) {
        uint32_t so = stage * STG_GU;
        size_t ko = (size_t)kt * 64;
        cpa(dA + so,              pA1 + ko);
        cpa(dA + so + 16,         pA1 + ko + 16);
        cpa(dA + so + 10240,      pA2 + ko);
        cpa(dA + so + 10240 + 16, pA2 + ko + 16);
        cpa(dB + so + 20480,      pG1 + ko);
        cpa(dB + so + 25600,      pG2 + ko);
        cpa(dB + so + 30720,      pU1 + ko);
        cpa(dB + so + 35840,      pU2 + ko);
        asm volatile("cp.async.commit_group;");
    };

    int lane = tid & 31, wid = tid >> 5;
    int wm = (wid & 3) * 32;
    int wn = (wid >> 2) * 32;
    int grp = lane >> 3, lr = lane & 7;
    uint32_t aoff[2], boff[2];
#pragma unroll
    for (int mf = 0; mf < 2; mf++)
        aoff[mf] = (uint32_t)((wm + mf * 16 + (grp & 1) * 8 + lr) * 80 + (grp >> 1) * 16);
#pragma unroll
    for (int nf2 = 0; nf2 < 2; nf2++)
        boff[nf2] = (uint32_t)((wn + nf2 * 16 + (grp >> 1) * 8 + lr) * 80 + (grp & 1) * 16);

    int cg0[2][4][4], cg1[2][4][4], cu0[2][4][4], cu1[2][4][4];
#pragma unroll
    for (int a = 0; a < 2; a++)
#pragma unroll
    for (int b = 0; b < 4; b++)
#pragma unroll
    for (int c = 0; c < 4; c++) {
        cg0[a][b][c] = 0; cg1[a][b][c] = 0; cu0[a][b][c] = 0; cu1[a][b][c] = 0;
    }

    const int KI = D_ / 64;
    issue(0, 0);
    for (int kt = 0; kt < KI; kt++) {
        int cur = kt & 1;
        if (kt + 1 < KI) {
            issue(cur ^ 1, kt + 1);
            asm volatile("cp.async.wait_group 1;");
        } else {
            asm volatile("cp.async.wait_group 0;");
        }
        __syncthreads();
        uint32_t st = sb + cur * STG_GU;
#pragma unroll
        for (int ks = 0; ks < 2; ks++) {
            uint32_t kb = ks * 32;
            uint32_t a1[2][4], a2[2][4], b1[2][4], b2[2][4];
#pragma unroll
            for (int mf = 0; mf < 2; mf++) {
                ldmx4(a1[mf], st + aoff[mf] + kb);
                ldmx4(a2[mf], st + 10240 + aoff[mf] + kb);
            }
            // gate
#pragma unroll
            for (int nf2 = 0; nf2 < 2; nf2++) {
                ldmx4(b1[nf2], st + 20480 + boff[nf2] + kb);
                ldmx4(b2[nf2], st + 25600 + boff[nf2] + kb);
            }
#pragma unroll
            for (int mf = 0; mf < 2; mf++)
#pragma unroll
            for (int nf2 = 0; nf2 < 2; nf2++)
#pragma unroll
            for (int j = 0; j < 2; j++) {
                int nf = nf2 * 2 + j;
                imma(cg0[mf][nf], a1[mf], &b1[nf2][2 * j]);
                imma(cg1[mf][nf], a1[mf], &b2[nf2][2 * j]);
                imma(cg1[mf][nf], a2[mf], &b1[nf2][2 * j]);
            }
            // up
#pragma unroll
            for (int nf2 = 0; nf2 < 2; nf2++) {
                ldmx4(b1[nf2], st + 30720 + boff[nf2] + kb);
                ldmx4(b2[nf2], st + 35840 + boff[nf2] + kb);
            }
#pragma unroll
            for (int mf = 0; mf < 2; mf++)
#pragma unroll
            for (int nf2 = 0; nf2 < 2; nf2++)
#pragma unroll
            for (int j = 0; j < 2; j++) {
                int nf = nf2 * 2 + j;
                imma(cu0[mf][nf], a1[mf], &b1[nf2][2 * j]);
                imma(cu1[mf][nf], a1[mf], &b2[nf2][2 * j]);
                imma(cu1[mf][nf], a2[mf], &b1[nf2][2 * j]);
            }
        }
        __syncthreads();
    }

    const float inv254 = 1.f / 254.f, inv127 = 1.f / 127.f;
#pragma unroll
    for (int mf = 0; mf < 2; mf++)
#pragma unroll
    for (int nf = 0; nf < 4; nf++) {
        int r = m0 + wm + mf * 16 + (lane >> 2);
        int c = n0 + wn + nf * 8 + (lane & 3) * 2;
        float sg0 = fmaxf(mG[c], 1e-20f) * inv127;
        float sg1 = fmaxf(mG[c + 1], 1e-20f) * inv127;
        float su0 = fmaxf(mU[c], 1e-20f) * inv127;
        float su1 = fmaxf(mU[c + 1], 1e-20f) * inv127;
#pragma unroll
        for (int h = 0; h < 2; h++) {
            int rr = r + h * 8;
            if (rr < M) {
                float sA = g_sx[stok[rr - m0]];
                float g0 = sA * sg0 * ((float)cg0[mf][nf][2 * h] + (float)cg1[mf][nf][2 * h] * inv254);
                float g1 = sA * sg1 * ((float)cg0[mf][nf][2 * h + 1] + (float)cg1[mf][nf][2 * h + 1] * inv254);
                float u0 = sA * su0 * ((float)cu0[mf][nf][2 * h] + (float)cu1[mf][nf][2 * h] * inv254);
                float u1 = sA * su1 * ((float)cu0[mf][nf][2 * h + 1] + (float)cu1[mf][nf][2 * h + 1] * inv254);
                float h0 = g0 / (1.f + expf(-g0)) * u0;
                float h1 = g1 / (1.f + expf(-g1)) * u1;
                *(float2*)(g_hf + (size_t)(base + rr) * Nn + c) = make_float2(h0, h1);
            }
        }
    }
}

// ---------------------------------------------------------------------------
// Down projection int8 IMMA GEMM. BM=128 BN=64 BK=64, 256 threads.
// Stage: A1 0, A2 10240, B1 20480, B2 25600; stride 30720.
// ---------------------------------------------------------------------------
#define STG_DN 30720
template<bool ROUTED>
__global__ void __launch_bounds__(256)
down_imma(float* __restrict__ out, int Kk) {
    int e    = ROUTED ? blockIdx.z : 0;
    int M    = ROUTED ? g_counts[e] : N_;
    int base = ROUTED ? g_offsets[e] : 0;
    int m0 = blockIdx.x * 128;
    if (m0 >= M) return;
    int n0 = blockIdx.y * 64;

    size_t eo = ROUTED ? (size_t)e * D_ * H_ : 0;
    const int8_t* B1 = (ROUTED ? g_qwd1 : g_qsd1) + eo;
    const int8_t* B2 = (ROUTED ? g_qwd2 : g_qsd2) + eo;
    const float* mB = ROUTED ? (g_mwd + e * D_) : g_msd;

    extern __shared__ char smem[];
    int tid = threadIdx.x;
    int rowA = tid >> 1, kqA = (tid & 1) * 32;
    int ra = m0 + rowA; if (ra > M - 1) ra = M - 1;
    const int8_t* pA1 = g_qh1 + (size_t)(base + ra) * Kk + kqA;
    const int8_t* pA2 = g_qh2 + (size_t)(base + ra) * Kk + kqA;
    int rowB = tid >> 2, kqB = (tid & 3) * 16;
    const int8_t* pB1 = B1 + (size_t)(n0 + rowB) * Kk + kqB;
    const int8_t* pB2 = B2 + (size_t)(n0 + rowB) * Kk + kqB;

    uint32_t sb = (uint32_t)__cvta_generic_to_shared(smem);
    uint32_t dA = sb + rowA * 80 + kqA;
    uint32_t dB = sb + rowB * 80 + kqB;

    auto issue = [&](int stage, int kt) {
        uint32_t so = stage * STG_DN;
        size_t ko = (size_t)kt * 64;
        cpa(dA + so,              pA1 + ko);
        cpa(dA + so + 16,         pA1 + ko + 16);
        cpa(dA + so + 10240,      pA2 + ko);
        cpa(dA + so + 10240 + 16, pA2 + ko + 16);
        cpa(dB + so + 20480,      pB1 + ko);
        cpa(dB + so + 25600,      pB2 + ko);
        asm volatile("cp.async.commit_group;");
    };

    int lane = tid & 31, wid = tid >> 5;
    int wm = (wid & 3) * 32;
    int wn = (wid >> 2) * 32;
    int grp = lane >> 3, lr = lane & 7;
    uint32_t aoff[2], boff[2];
#pragma unroll
    for (int mf = 0; mf < 2; mf++)
        aoff[mf] = (uint32_t)((wm + mf * 16 + (grp & 1) * 8 + lr) * 80 + (grp >> 1) * 16);
#pragma unroll
    for (int nf2 = 0; nf2 < 2; nf2++)
        boff[nf2] = (uint32_t)((wn + nf2 * 16 + (grp >> 1) * 8 + lr) * 80 + (grp & 1) * 16);

    int c0[2][4][4], c1[2][4][4];
#pragma unroll
    for (int a = 0; a < 2; a++)
#pragma unroll
    for (int b = 0; b < 4; b++)
#pragma unroll
    for (int c = 0; c < 4; c++) { c0[a][b][c] = 0; c1[a][b][c] = 0; }

    const int KI = Kk / 64;
    issue(0, 0);
    for (int kt = 0; kt < KI; kt++) {
        int cur = kt & 1;
        if (kt + 1 < KI) {
            issue(cur ^ 1, kt + 1);
            asm volatile("cp.async.wait_group 1;");
        } else {
            asm volatile("cp.async.wait_group 0;");
        }
        __syncthreads();
        uint32_t st = sb + cur * STG_DN;
#pragma unroll
        for (int ks = 0; ks < 2; ks++) {
            uint32_t kb = ks * 32;
            uint32_t a1[2][4], a2[2][4], b1[2][4], b2[2][4];
#pragma unroll
            for (int mf = 0; mf < 2; mf++) {
                ldmx4(a1[mf], st + aoff[mf] + kb);
                ldmx4(a2[mf], st + 10240 + aoff[mf] + kb);
            }
#pragma unroll
            for (int nf2 = 0; nf2 < 2; nf2++) {
                ldmx4(b1[nf2], st + 20480 + boff[nf2] + kb);
                ldmx4(b2[nf2], st + 25600 + boff[nf2] + kb);
            }
#pragma unroll
            for (int mf = 0; mf < 2; mf++)
#pragma unroll
            for (int nf2 = 0; nf2 < 2; nf2++)
#pragma unroll
            for (int j = 0; j < 2; j++) {
                int nf = nf2 * 2 + j;
                imma(c0[mf][nf], a1[mf], &b1[nf2][2 * j]);
                imma(c1[mf][nf], a1[mf], &b2[nf2][2 * j]);
                imma(c1[mf][nf], a2[mf], &b1[nf2][2 * j]);
            }
        }
        __syncthreads();
    }

    const float inv254 = 1.f / 254.f, inv127 = 1.f / 127.f;
#pragma unroll
    for (int mf = 0; mf < 2; mf++)
#pragma unroll
    for (int nf = 0; nf < 4; nf++) {
        int r = m0 + wm + mf * 16 + (lane >> 2);
        int c = n0 + wn + nf * 8 + (lane & 3) * 2;
        float sw0 = fmaxf(mB[c], 1e-20f) * inv127;
        float sw1 = fmaxf(mB[c + 1], 1e-20f) * inv127;
#pragma unroll
        for (int h = 0; h < 2; h++) {
            int rr = r + h * 8;
            if (rr < M) {
                float sA = g_sh[base + rr];
                float v0 = sA * sw0 * ((float)c0[mf][nf][2 * h] + (float)c1[mf][nf][2 * h] * inv254);
                float v1 = sA * sw1 * ((float)c0[mf][nf][2 * h + 1] + (float)c1[mf][nf][2 * h + 1] * inv254);
                if (ROUTED) {
                    int p = base + rr;
                    float gt = g_pgate[p];
                    float* op = out + (size_t)g_perm[p] * D_ + c;
                    atomicAdd(op,     v0 * gt);
                    atomicAdd(op + 1, v1 * gt);
                } else {
                    *(float2*)(out + (size_t)rr * D_ + c) = make_float2(v0, v1);
                }
            }
        }
    }
}

// ---------------------------------------------------------------------------
extern "C" void kernel_launch(void* const* d_in, const int* in_sizes, int n_in,
                              void* d_out, int out_size) {
    const float* x  = (const float*)d_in[0];
    const float* rw = (const float*)d_in[1];
    const float* wg = (const float*)d_in[2];
    const float* wu = (const float*)d_in[3];
    const float* wd = (const float*)d_in[4];
    const float* sg = (const float*)d_in[5];
    const float* su = (const float*)d_in[6];
    const float* sd = (const float*)d_in[7];
    float* out = (float*)d_out;

    const int SMEM_GU = 2 * STG_GU;   // 81920
    const int SMEM_DN = 2 * STG_DN;   // 61440
    cudaFuncSetAttribute(gateup_imma<false>, cudaFuncAttributeMaxDynamicSharedMemorySize, SMEM_GU);
    cudaFuncSetAttribute(gateup_imma<true>,  cudaFuncAttributeMaxDynamicSharedMemorySize, SMEM_GU);
    cudaFuncSetAttribute(down_imma<false>,   cudaFuncAttributeMaxDynamicSharedMemorySize, SMEM_DN);
    cudaFuncSetAttribute(down_imma<true>,    cudaFuncAttributeMaxDynamicSharedMemorySize, SMEM_DN);

    float *mwg, *mwu, *mwd, *msg, *msu, *msd;
    int8_t *qwg1, *qwg2, *qwu1, *qwu2, *qwd1, *qwd2;
    int8_t *qsg1, *qsg2, *qsu1, *qsu2, *qsd1, *qsd2;
    cudaGetSymbolAddress((void**)&mwg, g_mwg); cudaGetSymbolAddress((void**)&mwu, g_mwu);
    cudaGetSymbolAddress((void**)&mwd, g_mwd); cudaGetSymbolAddress((void**)&msg, g_msg);
    cudaGetSymbolAddress((void**)&msu, g_msu); cudaGetSymbolAddress((void**)&msd, g_msd);
    cudaGetSymbolAddress((void**)&qwg1, g_qwg1); cudaGetSymbolAddress((void**)&qwg2, g_qwg2);
    cudaGetSymbolAddress((void**)&qwu1, g_qwu1); cudaGetSymbolAddress((void**)&qwu2, g_qwu2);
    cudaGetSymbolAddress((void**)&qwd1, g_qwd1); cudaGetSymbolAddress((void**)&qwd2, g_qwd2);
    cudaGetSymbolAddress((void**)&qsg1, g_qsg1); cudaGetSymbolAddress((void**)&qsg2, g_qsg2);
    cudaGetSymbolAddress((void**)&qsu1, g_qsu1); cudaGetSymbolAddress((void**)&qsu2, g_qsu2);
    cudaGetSymbolAddress((void**)&qsd1, g_qsd1); cudaGetSymbolAddress((void**)&qsd2, g_qsd2);

    dim3 tb(32, 8);
    // per-output-feature maxima (atomicMax is idempotent across graph replays)
    wmaxcol<<<dim3(H_ / 32, D_ / 32, E_), tb>>>(wg, mwg, D_, H_);
    wmaxcol<<<dim3(H_ / 32, D_ / 32, E_), tb>>>(wu, mwu, D_, H_);
    wmaxcol<<<dim3(D_ / 32, H_ / 32, E_), tb>>>(wd, mwd, H_, D_);
    wmaxcol<<<dim3(HS_ / 32, D_ / 32, 1), tb>>>(sg, msg, D_, HS_);
    wmaxcol<<<dim3(HS_ / 32, D_ / 32, 1), tb>>>(su, msu, D_, HS_);
    wmaxcol<<<dim3(D_ / 32, HS_ / 32, 1), tb>>>(sd, msd, HS_, D_);
    // quantize + transpose to [n][k] int8 digit planes
    wquant<<<dim3(H_ / 32, D_ / 32, E_), tb>>>(wg, mwg, qwg1, qwg2, D_, H_);
    wquant<<<dim3(H_ / 32, D_ / 32, E_), tb>>>(wu, mwu, qwu1, qwu2, D_, H_);
    wquant<<<dim3(D_ / 32, H_ / 32, E_), tb>>>(wd, mwd, qwd1, qwd2, H_, D_);
    wquant<<<dim3(HS_ / 32, D_ / 32, 1), tb>>>(sg, msg, qsg1, qsg2, D_, HS_);
    wquant<<<dim3(HS_ / 32, D_ / 32, 1), tb>>>(su, msu, qsu1, qsu2, D_, HS_);
    wquant<<<dim3(D_ / 32, HS_ / 32, 1), tb>>>(sd, msd, qsd1, qsd2, HS_, D_);
    xquant<<<N_, 256>>>(x);

    router_kernel<<<N_ / 8, 256>>>(x, rw);
    build_lists_kernel<<<1, 256>>>();

    // Shared expert first: its down pass initializes every out element.
    gateup_imma<false><<<dim3(N_ / 128, HS_ / 64, 1), 256, SMEM_GU>>>(HS_);
    hquant<<<N_, 256>>>(HS_);
    down_imma<false><<<dim3(N_ / 128, D_ / 64, 1), 256, SMEM_DN>>>(out, HS_);

    // Routed experts: gathered grouped GEMMs + atomic scatter-add.
    gateup_imma<true><<<dim3(N_ / 128, H_ / 64, E_), 256, SMEM_GU>>>(H_);
    hquant<<<NK_, 256>>>(H_);
    down_imma<true><<<dim3(N_ / 128, D_ / 64, E_), 256, SMEM_DN>>>(out, H_);
}

// round 7
// speedup vs baseline: 2.5541x; 2.5541x over previous
#include <cuda_runtime.h>
#include <cuda_bf16.h>
#include <cstdint>

#define D_  2048
#define H_  1408
#define HS_ 2816
#define E_  8
#define N_  4096
#define NK_ (2*N_)

typedef __nv_bfloat16 bf16;

constexpr size_t EDH = (size_t)E_ * D_ * H_;
constexpr size_t DHS = (size_t)D_ * HS_;
constexpr size_t XSZ = (size_t)N_ * D_;
constexpr size_t HBUFSZ = 11534336;  // max(4096*2816, 8192*1408)

// -------- static scratch (no runtime allocation allowed) --------
__device__ bf16 g_wg_hi[EDH], g_wg_lo[EDH];   // transposed [E][H][D]
__device__ bf16 g_wu_hi[EDH], g_wu_lo[EDH];   // transposed [E][H][D]
__device__ bf16 g_wd_hi[EDH], g_wd_lo[EDH];   // transposed [E][D][H]
__device__ bf16 g_sg_hi[DHS], g_sg_lo[DHS];   // transposed [HS][D]
__device__ bf16 g_su_hi[DHS], g_su_lo[DHS];   // transposed [HS][D]
__device__ bf16 g_sd_hi[DHS], g_sd_lo[DHS];   // transposed [D][HS]
__device__ bf16 g_x_hi[XSZ], g_x_lo[XSZ];     // [N][D]
__device__ bf16 g_h_hi[HBUFSZ], g_h_lo[HBUFSZ];
__device__ int   g_perm[NK_];
__device__ float g_pgate[NK_];
__device__ int   g_counts[E_];
__device__ int   g_offsets[E_ + 1];
__device__ int   g_gidx[NK_];
__device__ float g_gval[NK_];

// -------- helpers --------
__device__ __forceinline__ void split_bf(float v, bf16& h, bf16& l) {
    h = __float2bfloat16(v);
    l = __float2bfloat16(v - __bfloat162float(h));
}
__device__ __forceinline__ void cpa(uint32_t d, const void* s) {
    asm volatile("cp.async.cg.shared.global [%0], [%1], 16;" :: "r"(d), "l"(s));
}
__device__ __forceinline__ void ldmx4(uint32_t* r, uint32_t a) {
    asm volatile("ldmatrix.sync.aligned.m8n8.x4.shared.b16 {%0,%1,%2,%3}, [%4];"
                 : "=r"(r[0]), "=r"(r[1]), "=r"(r[2]), "=r"(r[3]) : "r"(a));
}
__device__ __forceinline__ void mma16816(float* c, const uint32_t* a, const uint32_t* b) {
    asm volatile(
        "mma.sync.aligned.m16n8k16.row.col.f32.bf16.bf16.f32 "
        "{%0,%1,%2,%3},{%4,%5,%6,%7},{%8,%9},{%0,%1,%2,%3};"
        : "+f"(c[0]), "+f"(c[1]), "+f"(c[2]), "+f"(c[3])
        : "r"(a[0]), "r"(a[1]), "r"(a[2]), "r"(a[3]), "r"(b[0]), "r"(b[1]));
}

// -------- conversion kernels --------
__global__ void tconv(const float* __restrict__ src, bf16* __restrict__ dhi,
                      bf16* __restrict__ dlo, int R, int C) {
    __shared__ float t[32][33];
    size_t zo = (size_t)blockIdx.z * R * C;
    src += zo; dhi += zo; dlo += zo;
    int c0 = blockIdx.x * 32, r0 = blockIdx.y * 32;
    int tx = threadIdx.x, ty = threadIdx.y;
#pragma unroll
    for (int i = 0; i < 4; i++)
        t[ty + 8 * i][tx] = src[(size_t)(r0 + ty + 8 * i) * C + c0 + tx];
    __syncthreads();
#pragma unroll
    for (int i = 0; i < 4; i++) {
        float v = t[tx][ty + 8 * i];
        bf16 h, l; split_bf(v, h, l);
        size_t o = (size_t)(c0 + ty + 8 * i) * R + r0 + tx;
        dhi[o] = h; dlo[o] = l;
    }
}

__global__ void xconv(const float* __restrict__ x) {
    size_t i = (size_t)blockIdx.x * blockDim.x + threadIdx.x;
    float4 v = ((const float4*)x)[i];
    bf16 h0, l0, h1, l1, h2, l2, h3, l3;
    split_bf(v.x, h0, l0); split_bf(v.y, h1, l1);
    split_bf(v.z, h2, l2); split_bf(v.w, h3, l3);
    __nv_bfloat162* ph = (__nv_bfloat162*)(g_x_hi + 4 * i);
    __nv_bfloat162* pl = (__nv_bfloat162*)(g_x_lo + 4 * i);
    ph[0] = __halves2bfloat162(h0, h1); ph[1] = __halves2bfloat162(h2, h3);
    pl[0] = __halves2bfloat162(l0, l1); pl[1] = __halves2bfloat162(l2, l3);
}

// -------- router + list build (proven) --------
__global__ void router_kernel(const float* __restrict__ x, const float* __restrict__ rw) {
    int gw = (blockIdx.x * blockDim.x + threadIdx.x) >> 5;
    int lane = threadIdx.x & 31;
    if (gw >= N_) return;
    const float* xr = x + (size_t)gw * D_;
    float acc[E_];
#pragma unroll
    for (int e = 0; e < E_; e++) acc[e] = 0.f;
    for (int d = lane * 4; d < D_; d += 128) {
        float4 xv = *(const float4*)(xr + d);
#pragma unroll
        for (int e = 0; e < E_; e++) {
            float4 wv = *(const float4*)(rw + e * D_ + d);
            acc[e] += xv.x * wv.x + xv.y * wv.y + xv.z * wv.z + xv.w * wv.w;
        }
    }
#pragma unroll
    for (int e = 0; e < E_; e++) {
#pragma unroll
        for (int o = 16; o > 0; o >>= 1)
            acc[e] += __shfl_down_sync(0xffffffffu, acc[e], o);
    }
    if (lane == 0) {
        float mx = acc[0];
#pragma unroll
        for (int e = 1; e < E_; e++) mx = fmaxf(mx, acc[e]);
        float p[E_], s = 0.f;
#pragma unroll
        for (int e = 0; e < E_; e++) { p[e] = expf(acc[e] - mx); s += p[e]; }
        int i1 = 0;
#pragma unroll
        for (int e = 1; e < E_; e++) if (p[e] > p[i1]) i1 = e;
        int i2 = (i1 == 0) ? 1 : 0;
#pragma unroll
        for (int e = 0; e < E_; e++) if (e != i1 && p[e] > p[i2]) i2 = e;
        float g1 = p[i1] / s, g2 = p[i2] / s;
        float den = g1 + g2 + 1e-20f;
        g_gidx[2 * gw]     = i1; g_gval[2 * gw]     = g1 / den;
        g_gidx[2 * gw + 1] = i2; g_gval[2 * gw + 1] = g2 / den;
    }
}

__global__ void build_lists_kernel() {
    __shared__ int scnt[E_];
    __shared__ int soff[E_];
    int wid = threadIdx.x >> 5, lane = threadIdx.x & 31;
    if (wid < E_) {
        int c = 0;
        for (int base = 0; base < NK_; base += 32) {
            int flag = (g_gidx[base + lane] == wid);
            c += __popc(__ballot_sync(0xffffffffu, flag));
        }
        if (lane == 0) scnt[wid] = c;
    }
    __syncthreads();
    if (threadIdx.x == 0) {
        int s = 0;
        for (int e = 0; e < E_; e++) {
            soff[e] = s; g_offsets[e] = s; g_counts[e] = scnt[e]; s += scnt[e];
        }
        g_offsets[E_] = s;
    }
    __syncthreads();
    if (wid < E_) {
        int pos = soff[wid];
        for (int base = 0; base < NK_; base += 32) {
            int t = base + lane;
            int flag = (g_gidx[t] == wid);
            unsigned m = __ballot_sync(0xffffffffu, flag);
            if (flag) {
                int off = __popc(m & ((1u << lane) - 1u));
                g_perm[pos + off]  = t >> 1;
                g_pgate[pos + off] = g_gval[t];
            }
            pos += __popc(m);
        }
    }
}

// ---------------------------------------------------------------------------
// Fused gate/up GEMM + SiLU. BM=128 BN=128 BK=32, 512 threads (16 warps,
// 4m x 4n, warp tile 32x32), bf16x3 split.
// 3-stage cp.async pipeline, ONE __syncthreads per iteration.
// Stage (80B rows, 10240B/tile): Ahi 0, Alo 10240, Bg_hi 20480, Bg_lo 30720,
//   Bu_hi 40960, Bu_lo 51200. Stage stride 61440.
// ---------------------------------------------------------------------------
#define STG_GU 61440
template<bool ROUTED>
__global__ void __launch_bounds__(512)
gateup_mma(int Nn) {
    int e    = ROUTED ? blockIdx.z : 0;
    int M    = ROUTED ? g_counts[e] : N_;
    int base = ROUTED ? g_offsets[e] : 0;
    int m0 = blockIdx.x * 128;
    if (m0 >= M) return;
    int n0 = blockIdx.y * 128;

    size_t eoff = ROUTED ? (size_t)e * D_ * H_ : 0;
    const bf16* Bgh = (ROUTED ? g_wg_hi : g_sg_hi) + eoff;
    const bf16* Bgl = (ROUTED ? g_wg_lo : g_sg_lo) + eoff;
    const bf16* Buh = (ROUTED ? g_wu_hi : g_su_hi) + eoff;
    const bf16* Bul = (ROUTED ? g_wu_lo : g_su_lo) + eoff;

    extern __shared__ char smem[];
    __shared__ int stok[128];
    int tid = threadIdx.x;
    if (tid < 128) {
        int r = m0 + tid; if (r > M - 1) r = M - 1;
        stok[tid] = ROUTED ? g_perm[base + r] : r;
    }
    __syncthreads();

    int row = tid >> 2;           // 0..127
    int kq  = (tid & 3) * 16;     // byte offset within 64B of the row
    const char* pAh = (const char*)(g_x_hi + (size_t)stok[row] * D_) + kq;
    const char* pAl = (const char*)(g_x_lo + (size_t)stok[row] * D_) + kq;
    const char* pGh = (const char*)(Bgh + (size_t)(n0 + row) * D_) + kq;
    const char* pGl = (const char*)(Bgl + (size_t)(n0 + row) * D_) + kq;
    const char* pUh = (const char*)(Buh + (size_t)(n0 + row) * D_) + kq;
    const char* pUl = (const char*)(Bul + (size_t)(n0 + row) * D_) + kq;

    uint32_t sb = (uint32_t)__cvta_generic_to_shared(smem);
    uint32_t dr = sb + row * 80 + kq;

    auto issue = [&](int stage, int kt) {
        uint32_t so = stage * STG_GU;
        size_t ko = (size_t)kt * 64;
        cpa(dr + so,         pAh + ko);
        cpa(dr + so + 10240, pAl + ko);
        cpa(dr + so + 20480, pGh + ko);
        cpa(dr + so + 30720, pGl + ko);
        cpa(dr + so + 40960, pUh + ko);
        cpa(dr + so + 51200, pUl + ko);
        asm volatile("cp.async.commit_group;");
    };

    int lane = tid & 31, wid = tid >> 5;
    int wm = (wid & 3) * 32;
    int wn = (wid >> 2) * 32;
    int grp = lane >> 3, lr = lane & 7;
    uint32_t aoff[2], boff[2];
#pragma unroll
    for (int mf = 0; mf < 2; mf++)
        aoff[mf] = (uint32_t)((wm + mf * 16 + (grp & 1) * 8 + lr) * 80 + (grp >> 1) * 16);
#pragma unroll
    for (int nf2 = 0; nf2 < 2; nf2++)
        boff[nf2] = (uint32_t)((wn + nf2 * 16 + (grp >> 1) * 8 + lr) * 80 + (grp & 1) * 16);

    float cg[2][4][4], cu[2][4][4];
#pragma unroll
    for (int a = 0; a < 2; a++)
#pragma unroll
    for (int b = 0; b < 4; b++)
#pragma unroll
    for (int c = 0; c < 4; c++) { cg[a][b][c] = 0.f; cu[a][b][c] = 0.f; }

    const int KI = D_ / 32;   // 64
    issue(0, 0);
    issue(1, 1);
    int cur = 0;
    for (int kt = 0; kt < KI; kt++) {
        if (kt + 1 < KI) {
            asm volatile("cp.async.wait_group 1;");
        } else {
            asm volatile("cp.async.wait_group 0;");
        }
        __syncthreads();
        if (kt + 2 < KI) {
            int nstage = cur + 2; if (nstage >= 3) nstage -= 3;
            issue(nstage, kt + 2);
        }
        uint32_t st = sb + cur * STG_GU;
#pragma unroll
        for (int ks = 0; ks < 2; ks++) {
            uint32_t kb = ks * 32;
            uint32_t ah[2][4], al[2][4], bh[2][4], bl[2][4];
#pragma unroll
            for (int mf = 0; mf < 2; mf++) {
                ldmx4(ah[mf], st + aoff[mf] + kb);
                ldmx4(al[mf], st + 10240 + aoff[mf] + kb);
            }
            // gate matrix
#pragma unroll
            for (int nf2 = 0; nf2 < 2; nf2++) {
                ldmx4(bh[nf2], st + 20480 + boff[nf2] + kb);
                ldmx4(bl[nf2], st + 30720 + boff[nf2] + kb);
            }
#pragma unroll
            for (int mf = 0; mf < 2; mf++)
#pragma unroll
            for (int nf2 = 0; nf2 < 2; nf2++)
#pragma unroll
            for (int j = 0; j < 2; j++) {
                int nf = nf2 * 2 + j;
                mma16816(cg[mf][nf], ah[mf], &bh[nf2][2 * j]);
                mma16816(cg[mf][nf], al[mf], &bh[nf2][2 * j]);
                mma16816(cg[mf][nf], ah[mf], &bl[nf2][2 * j]);
            }
            // up matrix
#pragma unroll
            for (int nf2 = 0; nf2 < 2; nf2++) {
                ldmx4(bh[nf2], st + 40960 + boff[nf2] + kb);
                ldmx4(bl[nf2], st + 51200 + boff[nf2] + kb);
            }
#pragma unroll
            for (int mf = 0; mf < 2; mf++)
#pragma unroll
            for (int nf2 = 0; nf2 < 2; nf2++)
#pragma unroll
            for (int j = 0; j < 2; j++) {
                int nf = nf2 * 2 + j;
                mma16816(cu[mf][nf], ah[mf], &bh[nf2][2 * j]);
                mma16816(cu[mf][nf], al[mf], &bh[nf2][2 * j]);
                mma16816(cu[mf][nf], ah[mf], &bl[nf2][2 * j]);
            }
        }
        if (++cur == 3) cur = 0;
    }

#pragma unroll
    for (int mf = 0; mf < 2; mf++)
#pragma unroll
    for (int nf = 0; nf < 4; nf++) {
        int r = m0 + wm + mf * 16 + (lane >> 2);
        int c = n0 + wn + nf * 8 + (lane & 3) * 2;
#pragma unroll
        for (int h = 0; h < 2; h++) {
            int rr = r + h * 8;
            if (rr < M) {
                float gv0 = cg[mf][nf][2 * h],     gv1 = cg[mf][nf][2 * h + 1];
                float uv0 = cu[mf][nf][2 * h],     uv1 = cu[mf][nf][2 * h + 1];
                float h0 = gv0 / (1.f + expf(-gv0)) * uv0;
                float h1 = gv1 / (1.f + expf(-gv1)) * uv1;
                size_t o = (size_t)(base + rr) * Nn + c;
                bf16 hh0, hl0, hh1, hl1;
                split_bf(h0, hh0, hl0); split_bf(h1, hh1, hl1);
                *(__nv_bfloat162*)(g_h_hi + o) = __halves2bfloat162(hh0, hh1);
                *(__nv_bfloat162*)(g_h_lo + o) = __halves2bfloat162(hl0, hl1);
            }
        }
    }
}

// ---------------------------------------------------------------------------
// Down projection GEMM. BM=128 BN=128 BK=32, 512 threads, 3-stage pipeline.
// Stage: Ahi 0, Alo 10240, Bhi 20480, Blo 30720; stage stride 40960.
// ---------------------------------------------------------------------------
#define STG_DN 40960
template<bool ROUTED>
__global__ void __launch_bounds__(512)
down_mma(float* __restrict__ out, int Kk) {
    int e    = ROUTED ? blockIdx.z : 0;
    int M    = ROUTED ? g_counts[e] : N_;
    int base = ROUTED ? g_offsets[e] : 0;
    int m0 = blockIdx.x * 128;
    if (m0 >= M) return;
    int n0 = blockIdx.y * 128;

    size_t eoff = ROUTED ? (size_t)e * D_ * H_ : 0;
    const bf16* Bh = (ROUTED ? g_wd_hi : g_sd_hi) + eoff;
    const bf16* Bl = (ROUTED ? g_wd_lo : g_sd_lo) + eoff;

    extern __shared__ char smem[];
    int tid = threadIdx.x;
    int row = tid >> 2;
    int kq  = (tid & 3) * 16;
    int ra = m0 + row; if (ra > M - 1) ra = M - 1;
    const char* pAh = (const char*)(g_h_hi + (size_t)(base + ra) * Kk) + kq;
    const char* pAl = (const char*)(g_h_lo + (size_t)(base + ra) * Kk) + kq;
    const char* pBh = (const char*)(Bh + (size_t)(n0 + row) * Kk) + kq;
    const char* pBl = (const char*)(Bl + (size_t)(n0 + row) * Kk) + kq;

    uint32_t sb = (uint32_t)__cvta_generic_to_shared(smem);
    uint32_t dr = sb + row * 80 + kq;

    auto issue = [&](int stage, int kt) {
        uint32_t so = stage * STG_DN;
        size_t ko = (size_t)kt * 64;
        cpa(dr + so,         pAh + ko);
        cpa(dr + so + 10240, pAl + ko);
        cpa(dr + so + 20480, pBh + ko);
        cpa(dr + so + 30720, pBl + ko);
        asm volatile("cp.async.commit_group;");
    };

    int lane = tid & 31, wid = tid >> 5;
    int wm = (wid & 3) * 32;
    int wn = (wid >> 2) * 32;
    int grp = lane >> 3, lr = lane & 7;
    uint32_t aoff[2], boff[2];
#pragma unroll
    for (int mf = 0; mf < 2; mf++)
        aoff[mf] = (uint32_t)((wm + mf * 16 + (grp & 1) * 8 + lr) * 80 + (grp >> 1) * 16);
#pragma unroll
    for (int nf2 = 0; nf2 < 2; nf2++)
        boff[nf2] = (uint32_t)((wn + nf2 * 16 + (grp >> 1) * 8 + lr) * 80 + (grp & 1) * 16);

    float cd[2][4][4];
#pragma unroll
    for (int a = 0; a < 2; a++)
#pragma unroll
    for (int b = 0; b < 4; b++)
#pragma unroll
    for (int c = 0; c < 4; c++) cd[a][b][c] = 0.f;

    const int KI = Kk / 32;
    issue(0, 0);
    issue(1, 1);
    int cur = 0;
    for (int kt = 0; kt < KI; kt++) {
        if (kt + 1 < KI) {
            asm volatile("cp.async.wait_group 1;");
        } else {
            asm volatile("cp.async.wait_group 0;");
        }
        __syncthreads();
        if (kt + 2 < KI) {
            int nstage = cur + 2; if (nstage >= 3) nstage -= 3;
            issue(nstage, kt + 2);
        }
        uint32_t st = sb + cur * STG_DN;
#pragma unroll
        for (int ks = 0; ks < 2; ks++) {
            uint32_t kb = ks * 32;
            uint32_t ah[2][4], al[2][4], bh[2][4], bl[2][4];
#pragma unroll
            for (int mf = 0; mf < 2; mf++) {
                ldmx4(ah[mf], st + aoff[mf] + kb);
                ldmx4(al[mf], st + 10240 + aoff[mf] + kb);
            }
#pragma unroll
            for (int nf2 = 0; nf2 < 2; nf2++) {
                ldmx4(bh[nf2], st + 20480 + boff[nf2] + kb);
                ldmx4(bl[nf2], st + 30720 + boff[nf2] + kb);
            }
#pragma unroll
            for (int mf = 0; mf < 2; mf++)
#pragma unroll
            for (int nf2 = 0; nf2 < 2; nf2++)
#pragma unroll
            for (int j = 0; j < 2; j++) {
                int nf = nf2 * 2 + j;
                mma16816(cd[mf][nf], ah[mf], &bh[nf2][2 * j]);
                mma16816(cd[mf][nf], al[mf], &bh[nf2][2 * j]);
                mma16816(cd[mf][nf], ah[mf], &bl[nf2][2 * j]);
            }
        }
        if (++cur == 3) cur = 0;
    }

#pragma unroll
    for (int mf = 0; mf < 2; mf++)
#pragma unroll
    for (int nf = 0; nf < 4; nf++) {
        int r = m0 + wm + mf * 16 + (lane >> 2);
        int c = n0 + wn + nf * 8 + (lane & 3) * 2;
#pragma unroll
        for (int h = 0; h < 2; h++) {
            int rr = r + h * 8;
            if (rr < M) {
                float v0 = cd[mf][nf][2 * h], v1 = cd[mf][nf][2 * h + 1];
                if (ROUTED) {
                    int p = base + rr;
                    float gt = g_pgate[p];
                    float* op = out + (size_t)g_perm[p] * D_ + c;
                    atomicAdd(op,     v0 * gt);
                    atomicAdd(op + 1, v1 * gt);
                } else {
                    *(float2*)(out + (size_t)rr * D_ + c) = make_float2(v0, v1);
                }
            }
        }
    }
}

// ---------------------------------------------------------------------------
extern "C" void kernel_launch(void* const* d_in, const int* in_sizes, int n_in,
                              void* d_out, int out_size) {
    const float* x  = (const float*)d_in[0];
    const float* rw = (const float*)d_in[1];
    const float* wg = (const float*)d_in[2];
    const float* wu = (const float*)d_in[3];
    const float* wd = (const float*)d_in[4];
    const float* sg = (const float*)d_in[5];
    const float* su = (const float*)d_in[6];
    const float* sd = (const float*)d_in[7];
    float* out = (float*)d_out;

    const int SMEM_GU = 3 * STG_GU;   // 184320
    const int SMEM_DN = 3 * STG_DN;   // 122880
    cudaFuncSetAttribute(gateup_mma<false>, cudaFuncAttributeMaxDynamicSharedMemorySize, SMEM_GU);
    cudaFuncSetAttribute(gateup_mma<true>,  cudaFuncAttributeMaxDynamicSharedMemorySize, SMEM_GU);
    cudaFuncSetAttribute(down_mma<false>,   cudaFuncAttributeMaxDynamicSharedMemorySize, SMEM_DN);
    cudaFuncSetAttribute(down_mma<true>,    cudaFuncAttributeMaxDynamicSharedMemorySize, SMEM_DN);

    bf16 *wg_hi, *wg_lo, *wu_hi, *wu_lo, *wd_hi, *wd_lo;
    bf16 *sg_hi, *sg_lo, *su_hi, *su_lo, *sd_hi, *sd_lo;
    cudaGetSymbolAddress((void**)&wg_hi, g_wg_hi); cudaGetSymbolAddress((void**)&wg_lo, g_wg_lo);
    cudaGetSymbolAddress((void**)&wu_hi, g_wu_hi); cudaGetSymbolAddress((void**)&wu_lo, g_wu_lo);
    cudaGetSymbolAddress((void**)&wd_hi, g_wd_hi); cudaGetSymbolAddress((void**)&wd_lo, g_wd_lo);
    cudaGetSymbolAddress((void**)&sg_hi, g_sg_hi); cudaGetSymbolAddress((void**)&sg_lo, g_sg_lo);
    cudaGetSymbolAddress((void**)&su_hi, g_su_hi); cudaGetSymbolAddress((void**)&su_lo, g_su_lo);
    cudaGetSymbolAddress((void**)&sd_hi, g_sd_hi); cudaGetSymbolAddress((void**)&sd_lo, g_sd_lo);

    dim3 tb(32, 8);
    // Ordered so launch #6 (ncu -s 5 -c 1) is gateup_mma<false> — the GEMM.
    xconv<<<(N_ * D_ / 4) / 256, 256>>>(x);                              // 1
    tconv<<<dim3(HS_ / 32, D_ / 32, 1), tb>>>(sg, sg_hi, sg_lo, D_, HS_); // 2
    tconv<<<dim3(HS_ / 32, D_ / 32, 1), tb>>>(su, su_hi, su_lo, D_, HS_); // 3
    router_kernel<<<N_ / 8, 256>>>(x, rw);                               // 4
    build_lists_kernel<<<1, 256>>>();                                    // 5
    gateup_mma<false><<<dim3(N_ / 128, HS_ / 128, 1), 512, SMEM_GU>>>(HS_); // 6 <- profiled
    tconv<<<dim3(D_ / 32, HS_ / 32, 1), tb>>>(sd, sd_hi, sd_lo, HS_, D_);
    down_mma<false><<<dim3(N_ / 128, D_ / 128, 1), 512, SMEM_DN>>>(out, HS_);
    tconv<<<dim3(H_ / 32, D_ / 32, E_), tb>>>(wg, wg_hi, wg_lo, D_, H_);
    tconv<<<dim3(H_ / 32, D_ / 32, E_), tb>>>(wu, wu_hi, wu_lo, D_, H_);
    tconv<<<dim3(D_ / 32, H_ / 32, E_), tb>>>(wd, wd_hi, wd_lo, H_, D_);
    gateup_mma<true><<<dim3(N_ / 128, H_ / 128, E_), 512, SMEM_GU>>>(H_);
    down_mma<true><<<dim3(N_ / 128, D_ / 128, E_), 512, SMEM_DN>>>(out, H_);
}

// round 8
// speedup vs baseline: 3.4781x; 1.3618x over previous
#include <cuda_runtime.h>
#include <cuda_fp16.h>
#include <cstdint>

#define D_  2048
#define H_  1408
#define HS_ 2816
#define E_  8
#define N_  4096
#define NK_ (2*N_)

typedef __half fp16;

constexpr size_t EDH = (size_t)E_ * D_ * H_;
constexpr size_t DHS = (size_t)D_ * HS_;
constexpr size_t XSZ = (size_t)N_ * D_;
constexpr size_t HBUFSZ = 11534336;  // max(4096*2816, 8192*1408)

// -------- static scratch (no runtime allocation allowed) --------
__device__ fp16 g_wg[EDH];            // transposed [E][H][D], single fp16 plane
__device__ fp16 g_wu[EDH];
__device__ fp16 g_wd[EDH];            // transposed [E][D][H]
__device__ fp16 g_sg[DHS];            // transposed [HS][D]
__device__ fp16 g_su[DHS];
__device__ fp16 g_sd[DHS];            // transposed [D][HS]
__device__ fp16 g_x_hi[XSZ], g_x_lo[XSZ];     // [N][D] activation split
__device__ fp16 g_h_hi[HBUFSZ], g_h_lo[HBUFSZ];
__device__ int   g_perm[NK_];
__device__ float g_pgate[NK_];
__device__ int   g_counts[E_];
__device__ int   g_offsets[E_ + 1];
__device__ int   g_gidx[NK_];
__device__ float g_gval[NK_];

// -------- helpers --------
__device__ __forceinline__ void split_h(float v, fp16& h, fp16& l) {
    h = __float2half_rn(v);
    l = __float2half_rn(v - __half2float(h));
}
__device__ __forceinline__ void cpa(uint32_t d, const void* s) {
    asm volatile("cp.async.cg.shared.global [%0], [%1], 16;" :: "r"(d), "l"(s));
}
__device__ __forceinline__ void ldmx4(uint32_t* r, uint32_t a) {
    asm volatile("ldmatrix.sync.aligned.m8n8.x4.shared.b16 {%0,%1,%2,%3}, [%4];"
                 : "=r"(r[0]), "=r"(r[1]), "=r"(r[2]), "=r"(r[3]) : "r"(a));
}
__device__ __forceinline__ void mma16816(float* c, const uint32_t* a, const uint32_t* b) {
    asm volatile(
        "mma.sync.aligned.m16n8k16.row.col.f32.f16.f16.f32 "
        "{%0,%1,%2,%3},{%4,%5,%6,%7},{%8,%9},{%0,%1,%2,%3};"
        : "+f"(c[0]), "+f"(c[1]), "+f"(c[2]), "+f"(c[3])
        : "r"(a[0]), "r"(a[1]), "r"(a[2]), "r"(a[3]), "r"(b[0]), "r"(b[1]));
}

// -------- conversion kernels --------
// src [R][C] fp32 -> dst [C][R] single fp16 plane (transposed)
__global__ void tconvh(const float* __restrict__ src, fp16* __restrict__ dst,
                       int R, int C) {
    __shared__ float t[32][33];
    size_t zo = (size_t)blockIdx.z * R * C;
    src += zo; dst += zo;
    int c0 = blockIdx.x * 32, r0 = blockIdx.y * 32;
    int tx = threadIdx.x, ty = threadIdx.y;
#pragma unroll
    for (int i = 0; i < 4; i++)
        t[ty + 8 * i][tx] = src[(size_t)(r0 + ty + 8 * i) * C + c0 + tx];
    __syncthreads();
#pragma unroll
    for (int i = 0; i < 4; i++) {
        float v = t[tx][ty + 8 * i];
        dst[(size_t)(c0 + ty + 8 * i) * R + r0 + tx] = __float2half_rn(v);
    }
}

__global__ void xconv(const float* __restrict__ x) {
    size_t i = (size_t)blockIdx.x * blockDim.x + threadIdx.x;
    float4 v = ((const float4*)x)[i];
    fp16 h0, l0, h1, l1, h2, l2, h3, l3;
    split_h(v.x, h0, l0); split_h(v.y, h1, l1);
    split_h(v.z, h2, l2); split_h(v.w, h3, l3);
    __half2* ph = (__half2*)(g_x_hi + 4 * i);
    __half2* pl = (__half2*)(g_x_lo + 4 * i);
    ph[0] = __halves2half2(h0, h1); ph[1] = __halves2half2(h2, h3);
    pl[0] = __halves2half2(l0, l1); pl[1] = __halves2half2(l2, l3);
}

// -------- router + list build (proven) --------
__global__ void router_kernel(const float* __restrict__ x, const float* __restrict__ rw) {
    int gw = (blockIdx.x * blockDim.x + threadIdx.x) >> 5;
    int lane = threadIdx.x & 31;
    if (gw >= N_) return;
    const float* xr = x + (size_t)gw * D_;
    float acc[E_];
#pragma unroll
    for (int e = 0; e < E_; e++) acc[e] = 0.f;
    for (int d = lane * 4; d < D_; d += 128) {
        float4 xv = *(const float4*)(xr + d);
#pragma unroll
        for (int e = 0; e < E_; e++) {
            float4 wv = *(const float4*)(rw + e * D_ + d);
            acc[e] += xv.x * wv.x + xv.y * wv.y + xv.z * wv.z + xv.w * wv.w;
        }
    }
#pragma unroll
    for (int e = 0; e < E_; e++) {
#pragma unroll
        for (int o = 16; o > 0; o >>= 1)
            acc[e] += __shfl_down_sync(0xffffffffu, acc[e], o);
    }
    if (lane == 0) {
        float mx = acc[0];
#pragma unroll
        for (int e = 1; e < E_; e++) mx = fmaxf(mx, acc[e]);
        float p[E_], s = 0.f;
#pragma unroll
        for (int e = 0; e < E_; e++) { p[e] = expf(acc[e] - mx); s += p[e]; }
        int i1 = 0;
#pragma unroll
        for (int e = 1; e < E_; e++) if (p[e] > p[i1]) i1 = e;
        int i2 = (i1 == 0) ? 1 : 0;
#pragma unroll
        for (int e = 0; e < E_; e++) if (e != i1 && p[e] > p[i2]) i2 = e;
        float g1 = p[i1] / s, g2 = p[i2] / s;
        float den = g1 + g2 + 1e-20f;
        g_gidx[2 * gw]     = i1; g_gval[2 * gw]     = g1 / den;
        g_gidx[2 * gw + 1] = i2; g_gval[2 * gw + 1] = g2 / den;
    }
}

__global__ void build_lists_kernel() {
    __shared__ int scnt[E_];
    __shared__ int soff[E_];
    int wid = threadIdx.x >> 5, lane = threadIdx.x & 31;
    if (wid < E_) {
        int c = 0;
        for (int base = 0; base < NK_; base += 32) {
            int flag = (g_gidx[base + lane] == wid);
            c += __popc(__ballot_sync(0xffffffffu, flag));
        }
        if (lane == 0) scnt[wid] = c;
    }
    __syncthreads();
    if (threadIdx.x == 0) {
        int s = 0;
        for (int e = 0; e < E_; e++) {
            soff[e] = s; g_offsets[e] = s; g_counts[e] = scnt[e]; s += scnt[e];
        }
        g_offsets[E_] = s;
    }
    __syncthreads();
    if (wid < E_) {
        int pos = soff[wid];
        for (int base = 0; base < NK_; base += 32) {
            int t = base + lane;
            int flag = (g_gidx[t] == wid);
            unsigned m = __ballot_sync(0xffffffffu, flag);
            if (flag) {
                int off = __popc(m & ((1u << lane) - 1u));
                g_perm[pos + off]  = t >> 1;
                g_pgate[pos + off] = g_gval[t];
            }
            pos += __popc(m);
        }
    }
}

// ---------------------------------------------------------------------------
// Fused gate/up GEMM + SiLU. BM=128 BN=128 BK=32, 512 threads (16 warps,
// 4m x 4n, warp tile 32x32). fp16 asymmetric split: acc = a_hi*b + a_lo*b.
// 3-stage cp.async pipeline, ONE __syncthreads per iteration.
// Stage (80B rows, 10240B/tile): Ahi 0, Alo 10240, G 20480, U 30720.
// Stage stride 40960.
// ---------------------------------------------------------------------------
#define STG_GU 40960
template<bool ROUTED>
__global__ void __launch_bounds__(512)
gateup_mma(int Nn) {
    int e    = ROUTED ? blockIdx.z : 0;
    int M    = ROUTED ? g_counts[e] : N_;
    int base = ROUTED ? g_offsets[e] : 0;
    int m0 = blockIdx.x * 128;
    if (m0 >= M) return;
    int n0 = blockIdx.y * 128;

    size_t eoff = ROUTED ? (size_t)e * D_ * H_ : 0;
    const fp16* Bg = (ROUTED ? g_wg : g_sg) + eoff;
    const fp16* Bu = (ROUTED ? g_wu : g_su) + eoff;

    extern __shared__ char smem[];
    __shared__ int stok[128];
    int tid = threadIdx.x;
    if (tid < 128) {
        int r = m0 + tid; if (r > M - 1) r = M - 1;
        stok[tid] = ROUTED ? g_perm[base + r] : r;
    }
    __syncthreads();

    int row = tid >> 2;           // 0..127
    int kq  = (tid & 3) * 16;     // byte offset within 64B of the row
    const char* pAh = (const char*)(g_x_hi + (size_t)stok[row] * D_) + kq;
    const char* pAl = (const char*)(g_x_lo + (size_t)stok[row] * D_) + kq;
    const char* pG  = (const char*)(Bg + (size_t)(n0 + row) * D_) + kq;
    const char* pU  = (const char*)(Bu + (size_t)(n0 + row) * D_) + kq;

    uint32_t sb = (uint32_t)__cvta_generic_to_shared(smem);
    uint32_t dr = sb + row * 80 + kq;

    auto issue = [&](int stage, int kt) {
        uint32_t so = stage * STG_GU;
        size_t ko = (size_t)kt * 64;
        cpa(dr + so,         pAh + ko);
        cpa(dr + so + 10240, pAl + ko);
        cpa(dr + so + 20480, pG + ko);
        cpa(dr + so + 30720, pU + ko);
        asm volatile("cp.async.commit_group;");
    };

    int lane = tid & 31, wid = tid >> 5;
    int wm = (wid & 3) * 32;
    int wn = (wid >> 2) * 32;
    int grp = lane >> 3, lr = lane & 7;
    uint32_t aoff[2], boff[2];
#pragma unroll
    for (int mf = 0; mf < 2; mf++)
        aoff[mf] = (uint32_t)((wm + mf * 16 + (grp & 1) * 8 + lr) * 80 + (grp >> 1) * 16);
#pragma unroll
    for (int nf2 = 0; nf2 < 2; nf2++)
        boff[nf2] = (uint32_t)((wn + nf2 * 16 + (grp >> 1) * 8 + lr) * 80 + (grp & 1) * 16);

    float cg[2][4][4], cu[2][4][4];
#pragma unroll
    for (int a = 0; a < 2; a++)
#pragma unroll
    for (int b = 0; b < 4; b++)
#pragma unroll
    for (int c = 0; c < 4; c++) { cg[a][b][c] = 0.f; cu[a][b][c] = 0.f; }

    const int KI = D_ / 32;   // 64
    issue(0, 0);
    issue(1, 1);
    int cur = 0;
    for (int kt = 0; kt < KI; kt++) {
        if (kt + 1 < KI) {
            asm volatile("cp.async.wait_group 1;");
        } else {
            asm volatile("cp.async.wait_group 0;");
        }
        __syncthreads();
        if (kt + 2 < KI) {
            int nstage = cur + 2; if (nstage >= 3) nstage -= 3;
            issue(nstage, kt + 2);
        }
        uint32_t st = sb + cur * STG_GU;
#pragma unroll
        for (int ks = 0; ks < 2; ks++) {
            uint32_t kb = ks * 32;
            uint32_t ah[2][4], al[2][4], bg[2][4], bu[2][4];
#pragma unroll
            for (int mf = 0; mf < 2; mf++) {
                ldmx4(ah[mf], st + aoff[mf] + kb);
                ldmx4(al[mf], st + 10240 + aoff[mf] + kb);
            }
#pragma unroll
            for (int nf2 = 0; nf2 < 2; nf2++) {
                ldmx4(bg[nf2], st + 20480 + boff[nf2] + kb);
                ldmx4(bu[nf2], st + 30720 + boff[nf2] + kb);
            }
#pragma unroll
            for (int mf = 0; mf < 2; mf++)
#pragma unroll
            for (int nf2 = 0; nf2 < 2; nf2++)
#pragma unroll
            for (int j = 0; j < 2; j++) {
                int nf = nf2 * 2 + j;
                mma16816(cg[mf][nf], ah[mf], &bg[nf2][2 * j]);
                mma16816(cg[mf][nf], al[mf], &bg[nf2][2 * j]);
                mma16816(cu[mf][nf], ah[mf], &bu[nf2][2 * j]);
                mma16816(cu[mf][nf], al[mf], &bu[nf2][2 * j]);
            }
        }
        if (++cur == 3) cur = 0;
    }

#pragma unroll
    for (int mf = 0; mf < 2; mf++)
#pragma unroll
    for (int nf = 0; nf < 4; nf++) {
        int r = m0 + wm + mf * 16 + (lane >> 2);
        int c = n0 + wn + nf * 8 + (lane & 3) * 2;
#pragma unroll
        for (int h = 0; h < 2; h++) {
            int rr = r + h * 8;
            if (rr < M) {
                float gv0 = cg[mf][nf][2 * h],     gv1 = cg[mf][nf][2 * h + 1];
                float uv0 = cu[mf][nf][2 * h],     uv1 = cu[mf][nf][2 * h + 1];
                float h0 = gv0 / (1.f + expf(-gv0)) * uv0;
                float h1 = gv1 / (1.f + expf(-gv1)) * uv1;
                size_t o = (size_t)(base + rr) * Nn + c;
                fp16 hh0, hl0, hh1, hl1;
                split_h(h0, hh0, hl0); split_h(h1, hh1, hl1);
                *(__half2*)(g_h_hi + o) = __halves2half2(hh0, hh1);
                *(__half2*)(g_h_lo + o) = __halves2half2(hl0, hl1);
            }
        }
    }
}

// ---------------------------------------------------------------------------
// Down projection GEMM. BM=128 BN=128 BK=32, 512 threads, 3-stage pipeline.
// Stage: Ahi 0, Alo 10240, B 20480; stage stride 30720.
// ---------------------------------------------------------------------------
#define STG_DN 30720
template<bool ROUTED>
__global__ void __launch_bounds__(512)
down_mma(float* __restrict__ out, int Kk) {
    int e    = ROUTED ? blockIdx.z : 0;
    int M    = ROUTED ? g_counts[e] : N_;
    int base = ROUTED ? g_offsets[e] : 0;
    int m0 = blockIdx.x * 128;
    if (m0 >= M) return;
    int n0 = blockIdx.y * 128;

    size_t eoff = ROUTED ? (size_t)e * D_ * H_ : 0;
    const fp16* Bw = (ROUTED ? g_wd : g_sd) + eoff;

    extern __shared__ char smem[];
    int tid = threadIdx.x;
    int row = tid >> 2;
    int kq  = (tid & 3) * 16;
    int ra = m0 + row; if (ra > M - 1) ra = M - 1;
    const char* pAh = (const char*)(g_h_hi + (size_t)(base + ra) * Kk) + kq;
    const char* pAl = (const char*)(g_h_lo + (size_t)(base + ra) * Kk) + kq;
    const char* pB  = (const char*)(Bw + (size_t)(n0 + row) * Kk) + kq;

    uint32_t sb = (uint32_t)__cvta_generic_to_shared(smem);
    uint32_t dr = sb + row * 80 + kq;

    auto issue = [&](int stage, int kt) {
        uint32_t so = stage * STG_DN;
        size_t ko = (size_t)kt * 64;
        cpa(dr + so,         pAh + ko);
        cpa(dr + so + 10240, pAl + ko);
        cpa(dr + so + 20480, pB + ko);
        asm volatile("cp.async.commit_group;");
    };

    int lane = tid & 31, wid = tid >> 5;
    int wm = (wid & 3) * 32;
    int wn = (wid >> 2) * 32;
    int grp = lane >> 3, lr = lane & 7;
    uint32_t aoff[2], boff[2];
#pragma unroll
    for (int mf = 0; mf < 2; mf++)
        aoff[mf] = (uint32_t)((wm + mf * 16 + (grp & 1) * 8 + lr) * 80 + (grp >> 1) * 16);
#pragma unroll
    for (int nf2 = 0; nf2 < 2; nf2++)
        boff[nf2] = (uint32_t)((wn + nf2 * 16 + (grp >> 1) * 8 + lr) * 80 + (grp & 1) * 16);

    float cd[2][4][4];
#pragma unroll
    for (int a = 0; a < 2; a++)
#pragma unroll
    for (int b = 0; b < 4; b++)
#pragma unroll
    for (int c = 0; c < 4; c++) cd[a][b][c] = 0.f;

    const int KI = Kk / 32;
    issue(0, 0);
    issue(1, 1);
    int cur = 0;
    for (int kt = 0; kt < KI; kt++) {
        if (kt + 1 < KI) {
            asm volatile("cp.async.wait_group 1;");
        } else {
            asm volatile("cp.async.wait_group 0;");
        }
        __syncthreads();
        if (kt + 2 < KI) {
            int nstage = cur + 2; if (nstage >= 3) nstage -= 3;
            issue(nstage, kt + 2);
        }
        uint32_t st = sb + cur * STG_DN;
#pragma unroll
        for (int ks = 0; ks < 2; ks++) {
            uint32_t kb = ks * 32;
            uint32_t ah[2][4], al[2][4], bw[2][4];
#pragma unroll
            for (int mf = 0; mf < 2; mf++) {
                ldmx4(ah[mf], st + aoff[mf] + kb);
                ldmx4(al[mf], st + 10240 + aoff[mf] + kb);
            }
#pragma unroll
            for (int nf2 = 0; nf2 < 2; nf2++)
                ldmx4(bw[nf2], st + 20480 + boff[nf2] + kb);
#pragma unroll
            for (int mf = 0; mf < 2; mf++)
#pragma unroll
            for (int nf2 = 0; nf2 < 2; nf2++)
#pragma unroll
            for (int j = 0; j < 2; j++) {
                int nf = nf2 * 2 + j;
                mma16816(cd[mf][nf], ah[mf], &bw[nf2][2 * j]);
                mma16816(cd[mf][nf], al[mf], &bw[nf2][2 * j]);
            }
        }
        if (++cur == 3) cur = 0;
    }

#pragma unroll
    for (int mf = 0; mf < 2; mf++)
#pragma unroll
    for (int nf = 0; nf < 4; nf++) {
        int r = m0 + wm + mf * 16 + (lane >> 2);
        int c = n0 + wn + nf * 8 + (lane & 3) * 2;
#pragma unroll
        for (int h = 0; h < 2; h++) {
            int rr = r + h * 8;
            if (rr < M) {
                float v0 = cd[mf][nf][2 * h], v1 = cd[mf][nf][2 * h + 1];
                if (ROUTED) {
                    int p = base + rr;
                    float gt = g_pgate[p];
                    float* op = out + (size_t)g_perm[p] * D_ + c;
                    atomicAdd(op,     v0 * gt);
                    atomicAdd(op + 1, v1 * gt);
                } else {
                    *(float2*)(out + (size_t)rr * D_ + c) = make_float2(v0, v1);
                }
            }
        }
    }
}

// ---------------------------------------------------------------------------
extern "C" void kernel_launch(void* const* d_in, const int* in_sizes, int n_in,
                              void* d_out, int out_size) {
    const float* x  = (const float*)d_in[0];
    const float* rw = (const float*)d_in[1];
    const float* wg = (const float*)d_in[2];
    const float* wu = (const float*)d_in[3];
    const float* wd = (const float*)d_in[4];
    const float* sg = (const float*)d_in[5];
    const float* su = (const float*)d_in[6];
    const float* sd = (const float*)d_in[7];
    float* out = (float*)d_out;

    const int SMEM_GU = 3 * STG_GU;   // 122880
    const int SMEM_DN = 3 * STG_DN;   // 92160
    cudaFuncSetAttribute(gateup_mma<false>, cudaFuncAttributeMaxDynamicSharedMemorySize, SMEM_GU);
    cudaFuncSetAttribute(gateup_mma<true>,  cudaFuncAttributeMaxDynamicSharedMemorySize, SMEM_GU);
    cudaFuncSetAttribute(down_mma<false>,   cudaFuncAttributeMaxDynamicSharedMemorySize, SMEM_DN);
    cudaFuncSetAttribute(down_mma<true>,    cudaFuncAttributeMaxDynamicSharedMemorySize, SMEM_DN);

    fp16 *pwg, *pwu, *pwd, *psg, *psu, *psd;
    cudaGetSymbolAddress((void**)&pwg, g_wg);
    cudaGetSymbolAddress((void**)&pwu, g_wu);
    cudaGetSymbolAddress((void**)&pwd, g_wd);
    cudaGetSymbolAddress((void**)&psg, g_sg);
    cudaGetSymbolAddress((void**)&psu, g_su);
    cudaGetSymbolAddress((void**)&psd, g_sd);

    dim3 tb(32, 8);
    xconv<<<(N_ * D_ / 4) / 256, 256>>>(x);
    tconvh<<<dim3(HS_ / 32, D_ / 32, 1), tb>>>(sg, psg, D_, HS_);
    tconvh<<<dim3(HS_ / 32, D_ / 32, 1), tb>>>(su, psu, D_, HS_);
    router_kernel<<<N_ / 8, 256>>>(x, rw);
    build_lists_kernel<<<1, 256>>>();
    gateup_mma<false><<<dim3(N_ / 128, HS_ / 128, 1), 512, SMEM_GU>>>(HS_);
    tconvh<<<dim3(D_ / 32, HS_ / 32, 1), tb>>>(sd, psd, HS_, D_);
    down_mma<false><<<dim3(N_ / 128, D_ / 128, 1), 512, SMEM_DN>>>(out, HS_);
    tconvh<<<dim3(H_ / 32, D_ / 32, E_), tb>>>(wg, pwg, D_, H_);
    tconvh<<<dim3(H_ / 32, D_ / 32, E_), tb>>>(wu, pwu, D_, H_);
    tconvh<<<dim3(D_ / 32, H_ / 32, E_), tb>>>(wd, pwd, H_, D_);
    gateup_mma<true><<<dim3(N_ / 128, H_ / 128, E_), 512, SMEM_GU>>>(H_);
    down_mma<true><<<dim3(N_ / 128, D_ / 128, E_), 512, SMEM_DN>>>(out, H_);
}

// round 9
// speedup vs baseline: 5.6953x; 1.6375x over previous
#include <cuda_runtime.h>
#include <cuda_fp16.h>
#include <cstdint>

#define D_  2048
#define H_  1408
#define HS_ 2816
#define E_  8
#define N_  4096
#define NK_ (2*N_)

typedef __half fp16;

constexpr size_t EDH = (size_t)E_ * D_ * H_;
constexpr size_t DHS = (size_t)D_ * HS_;
constexpr size_t XSZ = (size_t)N_ * D_;
constexpr size_t HBUFSZ = 11534336;  // max(4096*2816, 8192*1408)

// -------- static scratch (no runtime allocation allowed) --------
__device__ fp16 g_wg[EDH];            // transposed [E][H][D]
__device__ fp16 g_wu[EDH];
__device__ fp16 g_wd[EDH];            // transposed [E][D][H]
__device__ fp16 g_sg[DHS];            // transposed [HS][D]
__device__ fp16 g_su[DHS];
__device__ fp16 g_sd[DHS];            // transposed [D][HS]
__device__ fp16 g_x[XSZ];             // [N][D]
__device__ fp16 g_h[HBUFSZ];
__device__ int   g_perm[NK_];
__device__ float g_pgate[NK_];
__device__ int   g_counts[E_];
__device__ int   g_offsets[E_ + 1];
__device__ int   g_gidx[NK_];
__device__ float g_gval[NK_];

// -------- helpers --------
__device__ __forceinline__ void cpa(uint32_t d, const void* s) {
    asm volatile("cp.async.cg.shared.global [%0], [%1], 16;" :: "r"(d), "l"(s));
}
__device__ __forceinline__ void ldmx4(uint32_t* r, uint32_t a) {
    asm volatile("ldmatrix.sync.aligned.m8n8.x4.shared.b16 {%0,%1,%2,%3}, [%4];"
                 : "=r"(r[0]), "=r"(r[1]), "=r"(r[2]), "=r"(r[3]) : "r"(a));
}
__device__ __forceinline__ void mma16816(float* c, const uint32_t* a, const uint32_t* b) {
    asm volatile(
        "mma.sync.aligned.m16n8k16.row.col.f32.f16.f16.f32 "
        "{%0,%1,%2,%3},{%4,%5,%6,%7},{%8,%9},{%0,%1,%2,%3};"
        : "+f"(c[0]), "+f"(c[1]), "+f"(c[2]), "+f"(c[3])
        : "r"(a[0]), "r"(a[1]), "r"(a[2]), "r"(a[3]), "r"(b[0]), "r"(b[1]));
}

// -------- conversion kernels --------
// src [R][C] fp32 -> dst [C][R] fp16 (transposed)
__global__ void tconvh(const float* __restrict__ src, fp16* __restrict__ dst,
                       int R, int C) {
    __shared__ float t[32][33];
    size_t zo = (size_t)blockIdx.z * R * C;
    src += zo; dst += zo;
    int c0 = blockIdx.x * 32, r0 = blockIdx.y * 32;
    int tx = threadIdx.x, ty = threadIdx.y;
#pragma unroll
    for (int i = 0; i < 4; i++)
        t[ty + 8 * i][tx] = src[(size_t)(r0 + ty + 8 * i) * C + c0 + tx];
    __syncthreads();
#pragma unroll
    for (int i = 0; i < 4; i++) {
        float v = t[tx][ty + 8 * i];
        dst[(size_t)(c0 + ty + 8 * i) * R + r0 + tx] = __float2half_rn(v);
    }
}

__global__ void xconv(const float* __restrict__ x) {
    size_t i = (size_t)blockIdx.x * blockDim.x + threadIdx.x;
    float4 v = ((const float4*)x)[i];
    __half2* p = (__half2*)(g_x + 4 * i);
    p[0] = __halves2half2(__float2half_rn(v.x), __float2half_rn(v.y));
    p[1] = __halves2half2(__float2half_rn(v.z), __float2half_rn(v.w));
}

// -------- router + list build (proven) --------
__global__ void router_kernel(const float* __restrict__ x, const float* __restrict__ rw) {
    int gw = (blockIdx.x * blockDim.x + threadIdx.x) >> 5;
    int lane = threadIdx.x & 31;
    if (gw >= N_) return;
    const float* xr = x + (size_t)gw * D_;
    float acc[E_];
#pragma unroll
    for (int e = 0; e < E_; e++) acc[e] = 0.f;
    for (int d = lane * 4; d < D_; d += 128) {
        float4 xv = *(const float4*)(xr + d);
#pragma unroll
        for (int e = 0; e < E_; e++) {
            float4 wv = *(const float4*)(rw + e * D_ + d);
            acc[e] += xv.x * wv.x + xv.y * wv.y + xv.z * wv.z + xv.w * wv.w;
        }
    }
#pragma unroll
    for (int e = 0; e < E_; e++) {
#pragma unroll
        for (int o = 16; o > 0; o >>= 1)
            acc[e] += __shfl_down_sync(0xffffffffu, acc[e], o);
    }
    if (lane == 0) {
        float mx = acc[0];
#pragma unroll
        for (int e = 1; e < E_; e++) mx = fmaxf(mx, acc[e]);
        float p[E_], s = 0.f;
#pragma unroll
        for (int e = 0; e < E_; e++) { p[e] = expf(acc[e] - mx); s += p[e]; }
        int i1 = 0;
#pragma unroll
        for (int e = 1; e < E_; e++) if (p[e] > p[i1]) i1 = e;
        int i2 = (i1 == 0) ? 1 : 0;
#pragma unroll
        for (int e = 0; e < E_; e++) if (e != i1 && p[e] > p[i2]) i2 = e;
        float g1 = p[i1] / s, g2 = p[i2] / s;
        float den = g1 + g2 + 1e-20f;
        g_gidx[2 * gw]     = i1; g_gval[2 * gw]     = g1 / den;
        g_gidx[2 * gw + 1] = i2; g_gval[2 * gw + 1] = g2 / den;
    }
}

__global__ void build_lists_kernel() {
    __shared__ int scnt[E_];
    __shared__ int soff[E_];
    int wid = threadIdx.x >> 5, lane = threadIdx.x & 31;
    if (wid < E_) {
        int c = 0;
        for (int base = 0; base < NK_; base += 32) {
            int flag = (g_gidx[base + lane] == wid);
            c += __popc(__ballot_sync(0xffffffffu, flag));
        }
        if (lane == 0) scnt[wid] = c;
    }
    __syncthreads();
    if (threadIdx.x == 0) {
        int s = 0;
        for (int e = 0; e < E_; e++) {
            soff[e] = s; g_offsets[e] = s; g_counts[e] = scnt[e]; s += scnt[e];
        }
        g_offsets[E_] = s;
    }
    __syncthreads();
    if (wid < E_) {
        int pos = soff[wid];
        for (int base = 0; base < NK_; base += 32) {
            int t = base + lane;
            int flag = (g_gidx[t] == wid);
            unsigned m = __ballot_sync(0xffffffffu, flag);
            if (flag) {
                int off = __popc(m & ((1u << lane) - 1u));
                g_perm[pos + off]  = t >> 1;
                g_pgate[pos + off] = g_gval[t];
            }
            pos += __popc(m);
        }
    }
}

// ---------------------------------------------------------------------------
// Fused gate/up GEMM + SiLU. BM=128 BN=128 BK=32, 512 threads (16 warps,
// 4m x 4n, warp tile 32x32), plain fp16 x fp16 -> fp32.
// 3-stage cp.async pipeline, ONE __syncthreads per iteration.
// Stage (80B rows, 10240B/tile): A 0, G 10240, U 20480. Stage stride 30720.
// ---------------------------------------------------------------------------
#define STG_GU 30720
template<bool ROUTED>
__global__ void __launch_bounds__(512)
gateup_mma(int Nn) {
    int e    = ROUTED ? blockIdx.z : 0;
    int M    = ROUTED ? g_counts[e] : N_;
    int base = ROUTED ? g_offsets[e] : 0;
    int m0 = blockIdx.x * 128;
    if (m0 >= M) return;
    int n0 = blockIdx.y * 128;

    size_t eoff = ROUTED ? (size_t)e * D_ * H_ : 0;
    const fp16* Bg = (ROUTED ? g_wg : g_sg) + eoff;
    const fp16* Bu = (ROUTED ? g_wu : g_su) + eoff;

    extern __shared__ char smem[];
    __shared__ int stok[128];
    int tid = threadIdx.x;
    if (tid < 128) {
        int r = m0 + tid; if (r > M - 1) r = M - 1;
        stok[tid] = ROUTED ? g_perm[base + r] : r;
    }
    __syncthreads();

    int row = tid >> 2;           // 0..127
    int kq  = (tid & 3) * 16;     // byte offset within 64B of the row
    const char* pA = (const char*)(g_x + (size_t)stok[row] * D_) + kq;
    const char* pG = (const char*)(Bg + (size_t)(n0 + row) * D_) + kq;
    const char* pU = (const char*)(Bu + (size_t)(n0 + row) * D_) + kq;

    uint32_t sb = (uint32_t)__cvta_generic_to_shared(smem);
    uint32_t dr = sb + row * 80 + kq;

    auto issue = [&](int stage, int kt) {
        uint32_t so = stage * STG_GU;
        size_t ko = (size_t)kt * 64;
        cpa(dr + so,         pA + ko);
        cpa(dr + so + 10240, pG + ko);
        cpa(dr + so + 20480, pU + ko);
        asm volatile("cp.async.commit_group;");
    };

    int lane = tid & 31, wid = tid >> 5;
    int wm = (wid & 3) * 32;
    int wn = (wid >> 2) * 32;
    int grp = lane >> 3, lr = lane & 7;
    uint32_t aoff[2], boff[2];
#pragma unroll
    for (int mf = 0; mf < 2; mf++)
        aoff[mf] = (uint32_t)((wm + mf * 16 + (grp & 1) * 8 + lr) * 80 + (grp >> 1) * 16);
#pragma unroll
    for (int nf2 = 0; nf2 < 2; nf2++)
        boff[nf2] = (uint32_t)((wn + nf2 * 16 + (grp >> 1) * 8 + lr) * 80 + (grp & 1) * 16);

    float cg[2][4][4], cu[2][4][4];
#pragma unroll
    for (int a = 0; a < 2; a++)
#pragma unroll
    for (int b = 0; b < 4; b++)
#pragma unroll
    for (int c = 0; c < 4; c++) { cg[a][b][c] = 0.f; cu[a][b][c] = 0.f; }

    const int KI = D_ / 32;   // 64
    issue(0, 0);
    issue(1, 1);
    int cur = 0;
    for (int kt = 0; kt < KI; kt++) {
        if (kt + 1 < KI) {
            asm volatile("cp.async.wait_group 1;");
        } else {
            asm volatile("cp.async.wait_group 0;");
        }
        __syncthreads();
        if (kt + 2 < KI) {
            int nstage = cur + 2; if (nstage >= 3) nstage -= 3;
            issue(nstage, kt + 2);
        }
        uint32_t st = sb + cur * STG_GU;
#pragma unroll
        for (int ks = 0; ks < 2; ks++) {
            uint32_t kb = ks * 32;
            uint32_t ah[2][4], bg[2][4], bu[2][4];
#pragma unroll
            for (int mf = 0; mf < 2; mf++)
                ldmx4(ah[mf], st + aoff[mf] + kb);
#pragma unroll
            for (int nf2 = 0; nf2 < 2; nf2++) {
                ldmx4(bg[nf2], st + 10240 + boff[nf2] + kb);
                ldmx4(bu[nf2], st + 20480 + boff[nf2] + kb);
            }
#pragma unroll
            for (int mf = 0; mf < 2; mf++)
#pragma unroll
            for (int nf2 = 0; nf2 < 2; nf2++)
#pragma unroll
            for (int j = 0; j < 2; j++) {
                int nf = nf2 * 2 + j;
                mma16816(cg[mf][nf], ah[mf], &bg[nf2][2 * j]);
                mma16816(cu[mf][nf], ah[mf], &bu[nf2][2 * j]);
            }
        }
        if (++cur == 3) cur = 0;
    }

#pragma unroll
    for (int mf = 0; mf < 2; mf++)
#pragma unroll
    for (int nf = 0; nf < 4; nf++) {
        int r = m0 + wm + mf * 16 + (lane >> 2);
        int c = n0 + wn + nf * 8 + (lane & 3) * 2;
#pragma unroll
        for (int h = 0; h < 2; h++) {
            int rr = r + h * 8;
            if (rr < M) {
                float gv0 = cg[mf][nf][2 * h],     gv1 = cg[mf][nf][2 * h + 1];
                float uv0 = cu[mf][nf][2 * h],     uv1 = cu[mf][nf][2 * h + 1];
                float h0 = gv0 / (1.f + expf(-gv0)) * uv0;
                float h1 = gv1 / (1.f + expf(-gv1)) * uv1;
                size_t o = (size_t)(base + rr) * Nn + c;
                *(__half2*)(g_h + o) =
                    __halves2half2(__float2half_rn(h0), __float2half_rn(h1));
            }
        }
    }
}

// ---------------------------------------------------------------------------
// Down projection GEMM. BM=128 BN=128 BK=32, 512 threads, 3-stage pipeline.
// Stage: A 0, B 10240; stage stride 20480.
// ---------------------------------------------------------------------------
#define STG_DN 20480
template<bool ROUTED>
__global__ void __launch_bounds__(512)
down_mma(float* __restrict__ out, int Kk) {
    int e    = ROUTED ? blockIdx.z : 0;
    int M    = ROUTED ? g_counts[e] : N_;
    int base = ROUTED ? g_offsets[e] : 0;
    int m0 = blockIdx.x * 128;
    if (m0 >= M) return;
    int n0 = blockIdx.y * 128;

    size_t eoff = ROUTED ? (size_t)e * D_ * H_ : 0;
    const fp16* Bw = (ROUTED ? g_wd : g_sd) + eoff;

    extern __shared__ char smem[];
    int tid = threadIdx.x;
    int row = tid >> 2;
    int kq  = (tid & 3) * 16;
    int ra = m0 + row; if (ra > M - 1) ra = M - 1;
    const char* pA = (const char*)(g_h + (size_t)(base + ra) * Kk) + kq;
    const char* pB = (const char*)(Bw + (size_t)(n0 + row) * Kk) + kq;

    uint32_t sb = (uint32_t)__cvta_generic_to_shared(smem);
    uint32_t dr = sb + row * 80 + kq;

    auto issue = [&](int stage, int kt) {
        uint32_t so = stage * STG_DN;
        size_t ko = (size_t)kt * 64;
        cpa(dr + so,         pA + ko);
        cpa(dr + so + 10240, pB + ko);
        asm volatile("cp.async.commit_group;");
    };

    int lane = tid & 31, wid = tid >> 5;
    int wm = (wid & 3) * 32;
    int wn = (wid >> 2) * 32;
    int grp = lane >> 3, lr = lane & 7;
    uint32_t aoff[2], boff[2];
#pragma unroll
    for (int mf = 0; mf < 2; mf++)
        aoff[mf] = (uint32_t)((wm + mf * 16 + (grp & 1) * 8 + lr) * 80 + (grp >> 1) * 16);
#pragma unroll
    for (int nf2 = 0; nf2 < 2; nf2++)
        boff[nf2] = (uint32_t)((wn + nf2 * 16 + (grp >> 1) * 8 + lr) * 80 + (grp & 1) * 16);

    float cd[2][4][4];
#pragma unroll
    for (int a = 0; a < 2; a++)
#pragma unroll
    for (int b = 0; b < 4; b++)
#pragma unroll
    for (int c = 0; c < 4; c++) cd[a][b][c] = 0.f;

    const int KI = Kk / 32;
    issue(0, 0);
    issue(1, 1);
    int cur = 0;
    for (int kt = 0; kt < KI; kt++) {
        if (kt + 1 < KI) {
            asm volatile("cp.async.wait_group 1;");
        } else {
            asm volatile("cp.async.wait_group 0;");
        }
        __syncthreads();
        if (kt + 2 < KI) {
            int nstage = cur + 2; if (nstage >= 3) nstage -= 3;
            issue(nstage, kt + 2);
        }
        uint32_t st = sb + cur * STG_DN;
#pragma unroll
        for (int ks = 0; ks < 2; ks++) {
            uint32_t kb = ks * 32;
            uint32_t ah[2][4], bw[2][4];
#pragma unroll
            for (int mf = 0; mf < 2; mf++)
                ldmx4(ah[mf], st + aoff[mf] + kb);
#pragma unroll
            for (int nf2 = 0; nf2 < 2; nf2++)
                ldmx4(bw[nf2], st + 10240 + boff[nf2] + kb);
#pragma unroll
            for (int mf = 0; mf < 2; mf++)
#pragma unroll
            for (int nf2 = 0; nf2 < 2; nf2++)
#pragma unroll
            for (int j = 0; j < 2; j++) {
                int nf = nf2 * 2 + j;
                mma16816(cd[mf][nf], ah[mf], &bw[nf2][2 * j]);
            }
        }
        if (++cur == 3) cur = 0;
    }

#pragma unroll
    for (int mf = 0; mf < 2; mf++)
#pragma unroll
    for (int nf = 0; nf < 4; nf++) {
        int r = m0 + wm + mf * 16 + (lane >> 2);
        int c = n0 + wn + nf * 8 + (lane & 3) * 2;
#pragma unroll
        for (int h = 0; h < 2; h++) {
            int rr = r + h * 8;
            if (rr < M) {
                float v0 = cd[mf][nf][2 * h], v1 = cd[mf][nf][2 * h + 1];
                if (ROUTED) {
                    int p = base + rr;
                    float gt = g_pgate[p];
                    float* op = out + (size_t)g_perm[p] * D_ + c;
                    atomicAdd(op,     v0 * gt);
                    atomicAdd(op + 1, v1 * gt);
                } else {
                    *(float2*)(out + (size_t)rr * D_ + c) = make_float2(v0, v1);
                }
            }
        }
    }
}

// ---------------------------------------------------------------------------
extern "C" void kernel_launch(void* const* d_in, const int* in_sizes, int n_in,
                              void* d_out, int out_size) {
    const float* x  = (const float*)d_in[0];
    const float* rw = (const float*)d_in[1];
    const float* wg = (const float*)d_in[2];
    const float* wu = (const float*)d_in[3];
    const float* wd = (const float*)d_in[4];
    const float* sg = (const float*)d_in[5];
    const float* su = (const float*)d_in[6];
    const float* sd = (const float*)d_in[7];
    float* out = (float*)d_out;

    const int SMEM_GU = 3 * STG_GU;   // 92160
    const int SMEM_DN = 3 * STG_DN;   // 61440
    cudaFuncSetAttribute(gateup_mma<false>, cudaFuncAttributeMaxDynamicSharedMemorySize, SMEM_GU);
    cudaFuncSetAttribute(gateup_mma<true>,  cudaFuncAttributeMaxDynamicSharedMemorySize, SMEM_GU);
    cudaFuncSetAttribute(down_mma<false>,   cudaFuncAttributeMaxDynamicSharedMemorySize, SMEM_DN);
    cudaFuncSetAttribute(down_mma<true>,    cudaFuncAttributeMaxDynamicSharedMemorySize, SMEM_DN);

    fp16 *pwg, *pwu, *pwd, *psg, *psu, *psd;
    cudaGetSymbolAddress((void**)&pwg, g_wg);
    cudaGetSymbolAddress((void**)&pwu, g_wu);
    cudaGetSymbolAddress((void**)&pwd, g_wd);
    cudaGetSymbolAddress((void**)&psg, g_sg);
    cudaGetSymbolAddress((void**)&psu, g_su);
    cudaGetSymbolAddress((void**)&psd, g_sd);

    dim3 tb(32, 8);
    xconv<<<(N_ * D_ / 4) / 256, 256>>>(x);
    tconvh<<<dim3(HS_ / 32, D_ / 32, 1), tb>>>(sg, psg, D_, HS_);
    tconvh<<<dim3(HS_ / 32, D_ / 32, 1), tb>>>(su, psu, D_, HS_);
    router_kernel<<<N_ / 8, 256>>>(x, rw);
    build_lists_kernel<<<1, 256>>>();
    gateup_mma<false><<<dim3(N_ / 128, HS_ / 128, 1), 512, SMEM_GU>>>(HS_);
    tconvh<<<dim3(D_ / 32, HS_ / 32, 1), tb>>>(sd, psd, HS_, D_);
    down_mma<false><<<dim3(N_ / 128, D_ / 128, 1), 512, SMEM_DN>>>(out, HS_);
    tconvh<<<dim3(H_ / 32, D_ / 32, E_), tb>>>(wg, pwg, D_, H_);
    tconvh<<<dim3(H_ / 32, D_ / 32, E_), tb>>>(wu, pwu, D_, H_);
    tconvh<<<dim3(D_ / 32, H_ / 32, E_), tb>>>(wd, pwd, H_, D_);
    gateup_mma<true><<<dim3(N_ / 128, H_ / 128, E_), 512, SMEM_GU>>>(H_);
    down_mma<true><<<dim3(N_ / 128, D_ / 128, E_), 512, SMEM_DN>>>(out, H_);
}

// round 10
// speedup vs baseline: 5.7718x; 1.0134x over previous
#include <cuda_runtime.h>
#include <cuda_fp16.h>
#include <cstdint>

#define D_  2048
#define H_  1408
#define HS_ 2816
#define E_  8
#define N_  4096
#define NK_ (2*N_)

typedef __half fp16;

constexpr size_t EDH = (size_t)E_ * D_ * H_;
constexpr size_t DHS = (size_t)D_ * HS_;
constexpr size_t XSZ = (size_t)N_ * D_;
constexpr size_t HBUFSZ = 11534336;  // max(4096*2816, 8192*1408)

// -------- static scratch (no runtime allocation allowed) --------
__device__ fp16 g_wg[EDH];            // transposed [E][H][D]
__device__ fp16 g_wu[EDH];
__device__ fp16 g_wd[EDH];            // transposed [E][D][H]
__device__ fp16 g_sg[DHS];            // transposed [HS][D]
__device__ fp16 g_su[DHS];
__device__ fp16 g_sd[DHS];            // transposed [D][HS]
__device__ fp16 g_x[XSZ];             // [N][D]
__device__ fp16 g_h[HBUFSZ];
__device__ int   g_perm[NK_];
__device__ float g_pgate[NK_];
__device__ int   g_counts[E_];
__device__ int   g_offsets[E_ + 1];
__device__ int   g_gidx[NK_];
__device__ float g_gval[NK_];

// -------- helpers --------
__device__ __forceinline__ void cpa(uint32_t d, const void* s) {
    asm volatile("cp.async.cg.shared.global [%0], [%1], 16;" :: "r"(d), "l"(s));
}
__device__ __forceinline__ void ldmx4(uint32_t* r, uint32_t a) {
    asm volatile("ldmatrix.sync.aligned.m8n8.x4.shared.b16 {%0,%1,%2,%3}, [%4];"
                 : "=r"(r[0]), "=r"(r[1]), "=r"(r[2]), "=r"(r[3]) : "r"(a));
}
__device__ __forceinline__ void mma16816(float* c, const uint32_t* a, const uint32_t* b) {
    asm volatile(
        "mma.sync.aligned.m16n8k16.row.col.f32.f16.f16.f32 "
        "{%0,%1,%2,%3},{%4,%5,%6,%7},{%8,%9},{%0,%1,%2,%3};"
        : "+f"(c[0]), "+f"(c[1]), "+f"(c[2]), "+f"(c[3])
        : "r"(a[0]), "r"(a[1]), "r"(a[2]), "r"(a[3]), "r"(b[0]), "r"(b[1]));
}

// -------- conversion kernels --------
// src [R][C] fp32 -> dst [C][R] fp16 (transposed).
// Tile 64 R-rows x 32 C-cols, block (32,8). Writes are half2 (two consecutive
// R positions) -> 128B per warp store. R % 64 == 0, C % 32 == 0 for all uses.
__global__ void tconvh(const float* __restrict__ src, fp16* __restrict__ dst,
                       int R, int C) {
    __shared__ float t[64][33];
    size_t zo = (size_t)blockIdx.z * R * C;
    src += zo; dst += zo;
    int c0 = blockIdx.x * 32, r0 = blockIdx.y * 64;
    int tx = threadIdx.x, ty = threadIdx.y;
#pragma unroll
    for (int i = 0; i < 8; i++)
        t[ty + 8 * i][tx] = src[(size_t)(r0 + ty + 8 * i) * C + c0 + tx];
    __syncthreads();
#pragma unroll
    for (int i = 0; i < 4; i++) {
        int cx = ty + 8 * i;
        float v0 = t[2 * tx][cx];
        float v1 = t[2 * tx + 1][cx];
        *(__half2*)(dst + (size_t)(c0 + cx) * R + r0 + 2 * tx) =
            __halves2half2(__float2half_rn(v0), __float2half_rn(v1));
    }
}

__global__ void xconv(const float* __restrict__ x) {
    size_t i = (size_t)blockIdx.x * blockDim.x + threadIdx.x;
    float4 v = ((const float4*)x)[i];
    __half2* p = (__half2*)(g_x + 4 * i);
    p[0] = __halves2half2(__float2half_rn(v.x), __float2half_rn(v.y));
    p[1] = __halves2half2(__float2half_rn(v.z), __float2half_rn(v.w));
}

// -------- router + list build (proven) --------
__global__ void router_kernel(const float* __restrict__ x, const float* __restrict__ rw) {
    int gw = (blockIdx.x * blockDim.x + threadIdx.x) >> 5;
    int lane = threadIdx.x & 31;
    if (gw >= N_) return;
    const float* xr = x + (size_t)gw * D_;
    float acc[E_];
#pragma unroll
    for (int e = 0; e < E_; e++) acc[e] = 0.f;
    for (int d = lane * 4; d < D_; d += 128) {
        float4 xv = *(const float4*)(xr + d);
#pragma unroll
        for (int e = 0; e < E_; e++) {
            float4 wv = *(const float4*)(rw + e * D_ + d);
            acc[e] += xv.x * wv.x + xv.y * wv.y + xv.z * wv.z + xv.w * wv.w;
        }
    }
#pragma unroll
    for (int e = 0; e < E_; e++) {
#pragma unroll
        for (int o = 16; o > 0; o >>= 1)
            acc[e] += __shfl_down_sync(0xffffffffu, acc[e], o);
    }
    if (lane == 0) {
        float mx = acc[0];
#pragma unroll
        for (int e = 1; e < E_; e++) mx = fmaxf(mx, acc[e]);
        float p[E_], s = 0.f;
#pragma unroll
        for (int e = 0; e < E_; e++) { p[e] = expf(acc[e] - mx); s += p[e]; }
        int i1 = 0;
#pragma unroll
        for (int e = 1; e < E_; e++) if (p[e] > p[i1]) i1 = e;
        int i2 = (i1 == 0) ? 1 : 0;
#pragma unroll
        for (int e = 0; e < E_; e++) if (e != i1 && p[e] > p[i2]) i2 = e;
        float g1 = p[i1] / s, g2 = p[i2] / s;
        float den = g1 + g2 + 1e-20f;
        g_gidx[2 * gw]     = i1; g_gval[2 * gw]     = g1 / den;
        g_gidx[2 * gw + 1] = i2; g_gval[2 * gw + 1] = g2 / den;
    }
}

__global__ void build_lists_kernel() {
    __shared__ int scnt[E_];
    __shared__ int soff[E_];
    int wid = threadIdx.x >> 5, lane = threadIdx.x & 31;
    if (wid < E_) {
        int c = 0;
        for (int base = 0; base < NK_; base += 32) {
            int flag = (g_gidx[base + lane] == wid);
            c += __popc(__ballot_sync(0xffffffffu, flag));
        }
        if (lane == 0) scnt[wid] = c;
    }
    __syncthreads();
    if (threadIdx.x == 0) {
        int s = 0;
        for (int e = 0; e < E_; e++) {
            soff[e] = s; g_offsets[e] = s; g_counts[e] = scnt[e]; s += scnt[e];
        }
        g_offsets[E_] = s;
    }
    __syncthreads();
    if (wid < E_) {
        int pos = soff[wid];
        for (int base = 0; base < NK_; base += 32) {
            int t = base + lane;
            int flag = (g_gidx[t] == wid);
            unsigned m = __ballot_sync(0xffffffffu, flag);
            if (flag) {
                int off = __popc(m & ((1u << lane) - 1u));
                g_perm[pos + off]  = t >> 1;
                g_pgate[pos + off] = g_gval[t];
            }
            pos += __popc(m);
        }
    }
}

// ---------------------------------------------------------------------------
// Fused gate/up GEMM + SiLU. BM=128 BN=128 BK=32, 512 threads (16 warps,
// 4m x 4n, warp tile 32x32), plain fp16 x fp16 -> fp32.
// 3-stage cp.async pipeline, ONE __syncthreads per iteration.
// Stage (80B rows, 10240B/tile): A 0, G 10240, U 20480. Stage stride 30720.
// ---------------------------------------------------------------------------
#define STG_GU 30720
template<bool ROUTED>
__global__ void __launch_bounds__(512)
gateup_mma(int Nn) {
    int e    = ROUTED ? blockIdx.z : 0;
    int M    = ROUTED ? g_counts[e] : N_;
    int base = ROUTED ? g_offsets[e] : 0;
    int m0 = blockIdx.x * 128;
    if (m0 >= M) return;
    int n0 = blockIdx.y * 128;

    size_t eoff = ROUTED ? (size_t)e * D_ * H_ : 0;
    const fp16* Bg = (ROUTED ? g_wg : g_sg) + eoff;
    const fp16* Bu = (ROUTED ? g_wu : g_su) + eoff;

    extern __shared__ char smem[];
    __shared__ int stok[128];
    int tid = threadIdx.x;
    if (tid < 128) {
        int r = m0 + tid; if (r > M - 1) r = M - 1;
        stok[tid] = ROUTED ? g_perm[base + r] : r;
    }
    __syncthreads();

    int row = tid >> 2;           // 0..127
    int kq  = (tid & 3) * 16;     // byte offset within 64B of the row
    const char* pA = (const char*)(g_x + (size_t)stok[row] * D_) + kq;
    const char* pG = (const char*)(Bg + (size_t)(n0 + row) * D_) + kq;
    const char* pU = (const char*)(Bu + (size_t)(n0 + row) * D_) + kq;

    uint32_t sb = (uint32_t)__cvta_generic_to_shared(smem);
    uint32_t dr = sb + row * 80 + kq;

    auto issue = [&](int stage, int kt) {
        uint32_t so = stage * STG_GU;
        size_t ko = (size_t)kt * 64;
        cpa(dr + so,         pA + ko);
        cpa(dr + so + 10240, pG + ko);
        cpa(dr + so + 20480, pU + ko);
        asm volatile("cp.async.commit_group;");
    };

    int lane = tid & 31, wid = tid >> 5;
    int wm = (wid & 3) * 32;
    int wn = (wid >> 2) * 32;
    int grp = lane >> 3, lr = lane & 7;
    uint32_t aoff[2], boff[2];
#pragma unroll
    for (int mf = 0; mf < 2; mf++)
        aoff[mf] = (uint32_t)((wm + mf * 16 + (grp & 1) * 8 + lr) * 80 + (grp >> 1) * 16);
#pragma unroll
    for (int nf2 = 0; nf2 < 2; nf2++)
        boff[nf2] = (uint32_t)((wn + nf2 * 16 + (grp >> 1) * 8 + lr) * 80 + (grp & 1) * 16);

    float cg[2][4][4], cu[2][4][4];
#pragma unroll
    for (int a = 0; a < 2; a++)
#pragma unroll
    for (int b = 0; b < 4; b++)
#pragma unroll
    for (int c = 0; c < 4; c++) { cg[a][b][c] = 0.f; cu[a][b][c] = 0.f; }

    const int KI = D_ / 32;   // 64
    issue(0, 0);
    issue(1, 1);
    int cur = 0;
    for (int kt = 0; kt < KI; kt++) {
        if (kt + 1 < KI) {
            asm volatile("cp.async.wait_group 1;");
        } else {
            asm volatile("cp.async.wait_group 0;");
        }
        __syncthreads();
        if (kt + 2 < KI) {
            int nstage = cur + 2; if (nstage >= 3) nstage -= 3;
            issue(nstage, kt + 2);
        }
        uint32_t st = sb + cur * STG_GU;
#pragma unroll
        for (int ks = 0; ks < 2; ks++) {
            uint32_t kb = ks * 32;
            uint32_t ah[2][4], bg[2][4], bu[2][4];
#pragma unroll
            for (int mf = 0; mf < 2; mf++)
                ldmx4(ah[mf], st + aoff[mf] + kb);
#pragma unroll
            for (int nf2 = 0; nf2 < 2; nf2++) {
                ldmx4(bg[nf2], st + 10240 + boff[nf2] + kb);
                ldmx4(bu[nf2], st + 20480 + boff[nf2] + kb);
            }
#pragma unroll
            for (int mf = 0; mf < 2; mf++)
#pragma unroll
            for (int nf2 = 0; nf2 < 2; nf2++)
#pragma unroll
            for (int j = 0; j < 2; j++) {
                int nf = nf2 * 2 + j;
                mma16816(cg[mf][nf], ah[mf], &bg[nf2][2 * j]);
                mma16816(cu[mf][nf], ah[mf], &bu[nf2][2 * j]);
            }
        }
        if (++cur == 3) cur = 0;
    }

#pragma unroll
    for (int mf = 0; mf < 2; mf++)
#pragma unroll
    for (int nf = 0; nf < 4; nf++) {
        int r = m0 + wm + mf * 16 + (lane >> 2);
        int c = n0 + wn + nf * 8 + (lane & 3) * 2;
#pragma unroll
        for (int h = 0; h < 2; h++) {
            int rr = r + h * 8;
            if (rr < M) {
                float gv0 = cg[mf][nf][2 * h],     gv1 = cg[mf][nf][2 * h + 1];
                float uv0 = cu[mf][nf][2 * h],     uv1 = cu[mf][nf][2 * h + 1];
                float h0 = gv0 / (1.f + expf(-gv0)) * uv0;
                float h1 = gv1 / (1.f + expf(-gv1)) * uv1;
                size_t o = (size_t)(base + rr) * Nn + c;
                *(__half2*)(g_h + o) =
                    __halves2half2(__float2half_rn(h0), __float2half_rn(h1));
            }
        }
    }
}

// ---------------------------------------------------------------------------
// Down projection GEMM. BM=128 BN=128 BK=32, 512 threads, 3-stage pipeline.
// Stage: A 0, B 10240; stage stride 20480.
// ---------------------------------------------------------------------------
#define STG_DN 20480
template<bool ROUTED>
__global__ void __launch_bounds__(512)
down_mma(float* __restrict__ out, int Kk) {
    int e    = ROUTED ? blockIdx.z : 0;
    int M    = ROUTED ? g_counts[e] : N_;
    int base = ROUTED ? g_offsets[e] : 0;
    int m0 = blockIdx.x * 128;
    if (m0 >= M) return;
    int n0 = blockIdx.y * 128;

    size_t eoff = ROUTED ? (size_t)e * D_ * H_ : 0;
    const fp16* Bw = (ROUTED ? g_wd : g_sd) + eoff;

    extern __shared__ char smem[];
    int tid = threadIdx.x;
    int row = tid >> 2;
    int kq  = (tid & 3) * 16;
    int ra = m0 + row; if (ra > M - 1) ra = M - 1;
    const char* pA = (const char*)(g_h + (size_t)(base + ra) * Kk) + kq;
    const char* pB = (const char*)(Bw + (size_t)(n0 + row) * Kk) + kq;

    uint32_t sb = (uint32_t)__cvta_generic_to_shared(smem);
    uint32_t dr = sb + row * 80 + kq;

    auto issue = [&](int stage, int kt) {
        uint32_t so = stage * STG_DN;
        size_t ko = (size_t)kt * 64;
        cpa(dr + so,         pA + ko);
        cpa(dr + so + 10240, pB + ko);
        asm volatile("cp.async.commit_group;");
    };

    int lane = tid & 31, wid = tid >> 5;
    int wm = (wid & 3) * 32;
    int wn = (wid >> 2) * 32;
    int grp = lane >> 3, lr = lane & 7;
    uint32_t aoff[2], boff[2];
#pragma unroll
    for (int mf = 0; mf < 2; mf++)
        aoff[mf] = (uint32_t)((wm + mf * 16 + (grp & 1) * 8 + lr) * 80 + (grp >> 1) * 16);
#pragma unroll
    for (int nf2 = 0; nf2 < 2; nf2++)
        boff[nf2] = (uint32_t)((wn + nf2 * 16 + (grp >> 1) * 8 + lr) * 80 + (grp & 1) * 16);

    float cd[2][4][4];
#pragma unroll
    for (int a = 0; a < 2; a++)
#pragma unroll
    for (int b = 0; b < 4; b++)
#pragma unroll
    for (int c = 0; c < 4; c++) cd[a][b][c] = 0.f;

    const int KI = Kk / 32;
    issue(0, 0);
    issue(1, 1);
    int cur = 0;
    for (int kt = 0; kt < KI; kt++) {
        if (kt + 1 < KI) {
            asm volatile("cp.async.wait_group 1;");
        } else {
            asm volatile("cp.async.wait_group 0;");
        }
        __syncthreads();
        if (kt + 2 < KI) {
            int nstage = cur + 2; if (nstage >= 3) nstage -= 3;
            issue(nstage, kt + 2);
        }
        uint32_t st = sb + cur * STG_DN;
#pragma unroll
        for (int ks = 0; ks < 2; ks++) {
            uint32_t kb = ks * 32;
            uint32_t ah[2][4], bw[2][4];
#pragma unroll
            for (int mf = 0; mf < 2; mf++)
                ldmx4(ah[mf], st + aoff[mf] + kb);
#pragma unroll
            for (int nf2 = 0; nf2 < 2; nf2++)
                ldmx4(bw[nf2], st + 10240 + boff[nf2] + kb);
#pragma unroll
            for (int mf = 0; mf < 2; mf++)
#pragma unroll
            for (int nf2 = 0; nf2 < 2; nf2++)
#pragma unroll
            for (int j = 0; j < 2; j++) {
                int nf = nf2 * 2 + j;
                mma16816(cd[mf][nf], ah[mf], &bw[nf2][2 * j]);
            }
        }
        if (++cur == 3) cur = 0;
    }

#pragma unroll
    for (int mf = 0; mf < 2; mf++)
#pragma unroll
    for (int nf = 0; nf < 4; nf++) {
        int r = m0 + wm + mf * 16 + (lane >> 2);
        int c = n0 + wn + nf * 8 + (lane & 3) * 2;
#pragma unroll
        for (int h = 0; h < 2; h++) {
            int rr = r + h * 8;
            if (rr < M) {
                float v0 = cd[mf][nf][2 * h], v1 = cd[mf][nf][2 * h + 1];
                if (ROUTED) {
                    int p = base + rr;
                    float gt = g_pgate[p];
                    float* op = out + (size_t)g_perm[p] * D_ + c;
                    atomicAdd(op,     v0 * gt);
                    atomicAdd(op + 1, v1 * gt);
                } else {
                    *(float2*)(out + (size_t)rr * D_ + c) = make_float2(v0, v1);
                }
            }
        }
    }
}

// ---------------------------------------------------------------------------
extern "C" void kernel_launch(void* const* d_in, const int* in_sizes, int n_in,
                              void* d_out, int out_size) {
    const float* x  = (const float*)d_in[0];
    const float* rw = (const float*)d_in[1];
    const float* wg = (const float*)d_in[2];
    const float* wu = (const float*)d_in[3];
    const float* wd = (const float*)d_in[4];
    const float* sg = (const float*)d_in[5];
    const float* su = (const float*)d_in[6];
    const float* sd = (const float*)d_in[7];
    float* out = (float*)d_out;

    const int SMEM_GU = 3 * STG_GU;   // 92160
    const int SMEM_DN = 3 * STG_DN;   // 61440
    cudaFuncSetAttribute(gateup_mma<false>, cudaFuncAttributeMaxDynamicSharedMemorySize, SMEM_GU);
    cudaFuncSetAttribute(gateup_mma<true>,  cudaFuncAttributeMaxDynamicSharedMemorySize, SMEM_GU);
    cudaFuncSetAttribute(down_mma<false>,   cudaFuncAttributeMaxDynamicSharedMemorySize, SMEM_DN);
    cudaFuncSetAttribute(down_mma<true>,    cudaFuncAttributeMaxDynamicSharedMemorySize, SMEM_DN);

    fp16 *pwg, *pwu, *pwd, *psg, *psu, *psd;
    cudaGetSymbolAddress((void**)&pwg, g_wg);
    cudaGetSymbolAddress((void**)&pwu, g_wu);
    cudaGetSymbolAddress((void**)&pwd, g_wd);
    cudaGetSymbolAddress((void**)&psg, g_sg);
    cudaGetSymbolAddress((void**)&psu, g_su);
    cudaGetSymbolAddress((void**)&psd, g_sd);

    dim3 tb(32, 8);
    // tconvh grid: (C/32, R/64, z)
    xconv<<<(N_ * D_ / 4) / 256, 256>>>(x);
    tconvh<<<dim3(HS_ / 32, D_ / 64, 1), tb>>>(sg, psg, D_, HS_);
    tconvh<<<dim3(HS_ / 32, D_ / 64, 1), tb>>>(su, psu, D_, HS_);
    router_kernel<<<N_ / 8, 256>>>(x, rw);
    build_lists_kernel<<<1, 256>>>();
    gateup_mma<false><<<dim3(N_ / 128, HS_ / 128, 1), 512, SMEM_GU>>>(HS_);
    tconvh<<<dim3(D_ / 32, HS_ / 64, 1), tb>>>(sd, psd, HS_, D_);
    down_mma<false><<<dim3(N_ / 128, D_ / 128, 1), 512, SMEM_DN>>>(out, HS_);
    tconvh<<<dim3(H_ / 32, D_ / 64, E_), tb>>>(wg, pwg, D_, H_);
    tconvh<<<dim3(H_ / 32, D_ / 64, E_), tb>>>(wu, pwu, D_, H_);
    tconvh<<<dim3(D_ / 32, H_ / 64, E_), tb>>>(wd, pwd, H_, D_);
    gateup_mma<true><<<dim3(N_ / 128, H_ / 128, E_), 512, SMEM_GU>>>(H_);
    down_mma<true><<<dim3(N_ / 128, D_ / 128, E_), 512, SMEM_DN>>>(out, H_);
}

// round 11
// speedup vs baseline: 6.5292x; 1.1312x over previous
#include <cuda_runtime.h>
#include <cuda_fp16.h>
#include <cstdint>

#define D_  2048
#define H_  1408
#define HS_ 2816
#define E_  8
#define N_  4096
#define NK_ (2*N_)

typedef __half fp16;

constexpr size_t EDH = (size_t)E_ * D_ * H_;
constexpr size_t DHS = (size_t)D_ * HS_;
constexpr size_t XSZ = (size_t)N_ * D_;

// -------- static scratch (no runtime allocation allowed) --------
__device__ fp16 g_wg[EDH];            // transposed [E][H][D]
__device__ fp16 g_wu[EDH];
__device__ fp16 g_wd[EDH];            // transposed [E][D][H]
__device__ fp16 g_sg[DHS];            // transposed [HS][D]
__device__ fp16 g_su[DHS];
__device__ fp16 g_sd[DHS];            // transposed [D][HS]
__device__ fp16 g_x[XSZ];             // [N][D]
__device__ fp16 g_hs[(size_t)N_ * HS_];    // shared-expert hidden
__device__ fp16 g_hr[(size_t)NK_ * H_];    // routed hidden
__device__ int   g_perm[NK_];
__device__ float g_pgate[NK_];
__device__ int   g_counts[E_];
__device__ int   g_offsets[E_ + 1];
__device__ int   g_gidx[NK_];
__device__ float g_gval[NK_];

// -------- helpers --------
__device__ __forceinline__ void cpa(uint32_t d, const void* s) {
    asm volatile("cp.async.cg.shared.global [%0], [%1], 16;" :: "r"(d), "l"(s));
}
__device__ __forceinline__ void ldmx4(uint32_t* r, uint32_t a) {
    asm volatile("ldmatrix.sync.aligned.m8n8.x4.shared.b16 {%0,%1,%2,%3}, [%4];"
                 : "=r"(r[0]), "=r"(r[1]), "=r"(r[2]), "=r"(r[3]) : "r"(a));
}
__device__ __forceinline__ void mma16816(float* c, const uint32_t* a, const uint32_t* b) {
    asm volatile(
        "mma.sync.aligned.m16n8k16.row.col.f32.f16.f16.f32 "
        "{%0,%1,%2,%3},{%4,%5,%6,%7},{%8,%9},{%0,%1,%2,%3};"
        : "+f"(c[0]), "+f"(c[1]), "+f"(c[2]), "+f"(c[3])
        : "r"(a[0]), "r"(a[1]), "r"(a[2]), "r"(a[3]), "r"(b[0]), "r"(b[1]));
}

// -------- conversion kernels --------
__global__ void tconvh(const float* __restrict__ src, fp16* __restrict__ dst,
                       int R, int C) {
    __shared__ float t[64][33];
    size_t zo = (size_t)blockIdx.z * R * C;
    src += zo; dst += zo;
    int c0 = blockIdx.x * 32, r0 = blockIdx.y * 64;
    int tx = threadIdx.x, ty = threadIdx.y;
#pragma unroll
    for (int i = 0; i < 8; i++)
        t[ty + 8 * i][tx] = src[(size_t)(r0 + ty + 8 * i) * C + c0 + tx];
    __syncthreads();
#pragma unroll
    for (int i = 0; i < 4; i++) {
        int cx = ty + 8 * i;
        float v0 = t[2 * tx][cx];
        float v1 = t[2 * tx + 1][cx];
        *(__half2*)(dst + (size_t)(c0 + cx) * R + r0 + 2 * tx) =
            __halves2half2(__float2half_rn(v0), __float2half_rn(v1));
    }
}

__global__ void xconv(const float* __restrict__ x) {
    size_t i = (size_t)blockIdx.x * blockDim.x + threadIdx.x;
    float4 v = ((const float4*)x)[i];
    __half2* p = (__half2*)(g_x + 4 * i);
    p[0] = __halves2half2(__float2half_rn(v.x), __float2half_rn(v.y));
    p[1] = __halves2half2(__float2half_rn(v.z), __float2half_rn(v.w));
}

// -------- router + list build (proven) --------
__global__ void router_kernel(const float* __restrict__ x, const float* __restrict__ rw) {
    int gw = (blockIdx.x * blockDim.x + threadIdx.x) >> 5;
    int lane = threadIdx.x & 31;
    if (gw >= N_) return;
    const float* xr = x + (size_t)gw * D_;
    float acc[E_];
#pragma unroll
    for (int e = 0; e < E_; e++) acc[e] = 0.f;
    for (int d = lane * 4; d < D_; d += 128) {
        float4 xv = *(const float4*)(xr + d);
#pragma unroll
        for (int e = 0; e < E_; e++) {
            float4 wv = *(const float4*)(rw + e * D_ + d);
            acc[e] += xv.x * wv.x + xv.y * wv.y + xv.z * wv.z + xv.w * wv.w;
        }
    }
#pragma unroll
    for (int e = 0; e < E_; e++) {
#pragma unroll
        for (int o = 16; o > 0; o >>= 1)
            acc[e] += __shfl_down_sync(0xffffffffu, acc[e], o);
    }
    if (lane == 0) {
        float mx = acc[0];
#pragma unroll
        for (int e = 1; e < E_; e++) mx = fmaxf(mx, acc[e]);
        float p[E_], s = 0.f;
#pragma unroll
        for (int e = 0; e < E_; e++) { p[e] = expf(acc[e] - mx); s += p[e]; }
        int i1 = 0;
#pragma unroll
        for (int e = 1; e < E_; e++) if (p[e] > p[i1]) i1 = e;
        int i2 = (i1 == 0) ? 1 : 0;
#pragma unroll
        for (int e = 0; e < E_; e++) if (e != i1 && p[e] > p[i2]) i2 = e;
        float g1 = p[i1] / s, g2 = p[i2] / s;
        float den = g1 + g2 + 1e-20f;
        g_gidx[2 * gw]     = i1; g_gval[2 * gw]     = g1 / den;
        g_gidx[2 * gw + 1] = i2; g_gval[2 * gw + 1] = g2 / den;
    }
}

__global__ void build_lists_kernel() {
    __shared__ int scnt[E_];
    __shared__ int soff[E_];
    int wid = threadIdx.x >> 5, lane = threadIdx.x & 31;
    if (wid < E_) {
        int c = 0;
        for (int base = 0; base < NK_; base += 32) {
            int flag = (g_gidx[base + lane] == wid);
            c += __popc(__ballot_sync(0xffffffffu, flag));
        }
        if (lane == 0) scnt[wid] = c;
    }
    __syncthreads();
    if (threadIdx.x == 0) {
        int s = 0;
        for (int e = 0; e < E_; e++) {
            soff[e] = s; g_offsets[e] = s; g_counts[e] = scnt[e]; s += scnt[e];
        }
        g_offsets[E_] = s;
    }
    __syncthreads();
    if (wid < E_) {
        int pos = soff[wid];
        for (int base = 0; base < NK_; base += 32) {
            int t = base + lane;
            int flag = (g_gidx[t] == wid);
            unsigned m = __ballot_sync(0xffffffffu, flag);
            if (flag) {
                int off = __popc(m & ((1u << lane) - 1u));
                g_perm[pos + off]  = t >> 1;
                g_pgate[pos + off] = g_gval[t];
            }
            pos += __popc(m);
        }
    }
}

// ---------------------------------------------------------------------------
// Fused gate/up GEMM + SiLU -> hbuf. BM=128 BN=128 BK=32, 512 threads,
// fp16 x fp16 -> fp32, 3-stage cp.async pipeline, one sync per iter.
// Stage: A 0, G 10240, U 20480. Stage stride 30720. 80B rows.
// ---------------------------------------------------------------------------
#define STG_GU 30720
template<bool ROUTED>
__global__ void __launch_bounds__(512)
gateup_mma(fp16* __restrict__ hbuf, int Nn) {
    int e    = ROUTED ? blockIdx.z : 0;
    int M    = ROUTED ? g_counts[e] : N_;
    int base = ROUTED ? g_offsets[e] : 0;
    int m0 = blockIdx.x * 128;
    if (m0 >= M) return;
    int n0 = blockIdx.y * 128;

    size_t eoff = ROUTED ? (size_t)e * D_ * H_ : 0;
    const fp16* Bg = (ROUTED ? g_wg : g_sg) + eoff;
    const fp16* Bu = (ROUTED ? g_wu : g_su) + eoff;

    extern __shared__ char smem[];
    __shared__ int stok[128];
    int tid = threadIdx.x;
    if (tid < 128) {
        int r = m0 + tid; if (r > M - 1) r = M - 1;
        stok[tid] = ROUTED ? g_perm[base + r] : r;
    }
    __syncthreads();

    int row = tid >> 2;
    int kq  = (tid & 3) * 16;
    const char* pA = (const char*)(g_x + (size_t)stok[row] * D_) + kq;
    const char* pG = (const char*)(Bg + (size_t)(n0 + row) * D_) + kq;
    const char* pU = (const char*)(Bu + (size_t)(n0 + row) * D_) + kq;

    uint32_t sb = (uint32_t)__cvta_generic_to_shared(smem);
    uint32_t dr = sb + row * 80 + kq;

    auto issue = [&](int stage, int kt) {
        uint32_t so = stage * STG_GU;
        size_t ko = (size_t)kt * 64;
        cpa(dr + so,         pA + ko);
        cpa(dr + so + 10240, pG + ko);
        cpa(dr + so + 20480, pU + ko);
        asm volatile("cp.async.commit_group;");
    };

    int lane = tid & 31, wid = tid >> 5;
    int wm = (wid & 3) * 32;
    int wn = (wid >> 2) * 32;
    int grp = lane >> 3, lr = lane & 7;
    uint32_t aoff[2], boff[2];
#pragma unroll
    for (int mf = 0; mf < 2; mf++)
        aoff[mf] = (uint32_t)((wm + mf * 16 + (grp & 1) * 8 + lr) * 80 + (grp >> 1) * 16);
#pragma unroll
    for (int nf2 = 0; nf2 < 2; nf2++)
        boff[nf2] = (uint32_t)((wn + nf2 * 16 + (grp >> 1) * 8 + lr) * 80 + (grp & 1) * 16);

    float cg[2][4][4], cu[2][4][4];
#pragma unroll
    for (int a = 0; a < 2; a++)
#pragma unroll
    for (int b = 0; b < 4; b++)
#pragma unroll
    for (int c = 0; c < 4; c++) { cg[a][b][c] = 0.f; cu[a][b][c] = 0.f; }

    const int KI = D_ / 32;   // 64
    issue(0, 0);
    issue(1, 1);
    int cur = 0;
    for (int kt = 0; kt < KI; kt++) {
        if (kt + 1 < KI) {
            asm volatile("cp.async.wait_group 1;");
        } else {
            asm volatile("cp.async.wait_group 0;");
        }
        __syncthreads();
        if (kt + 2 < KI) {
            int nstage = cur + 2; if (nstage >= 3) nstage -= 3;
            issue(nstage, kt + 2);
        }
        uint32_t st = sb + cur * STG_GU;
#pragma unroll
        for (int ks = 0; ks < 2; ks++) {
            uint32_t kb = ks * 32;
            uint32_t ah[2][4], bg[2][4], bu[2][4];
#pragma unroll
            for (int mf = 0; mf < 2; mf++)
                ldmx4(ah[mf], st + aoff[mf] + kb);
#pragma unroll
            for (int nf2 = 0; nf2 < 2; nf2++) {
                ldmx4(bg[nf2], st + 10240 + boff[nf2] + kb);
                ldmx4(bu[nf2], st + 20480 + boff[nf2] + kb);
            }
#pragma unroll
            for (int mf = 0; mf < 2; mf++)
#pragma unroll
            for (int nf2 = 0; nf2 < 2; nf2++)
#pragma unroll
            for (int j = 0; j < 2; j++) {
                int nf = nf2 * 2 + j;
                mma16816(cg[mf][nf], ah[mf], &bg[nf2][2 * j]);
                mma16816(cu[mf][nf], ah[mf], &bu[nf2][2 * j]);
            }
        }
        if (++cur == 3) cur = 0;
    }

#pragma unroll
    for (int mf = 0; mf < 2; mf++)
#pragma unroll
    for (int nf = 0; nf < 4; nf++) {
        int r = m0 + wm + mf * 16 + (lane >> 2);
        int c = n0 + wn + nf * 8 + (lane & 3) * 2;
#pragma unroll
        for (int h = 0; h < 2; h++) {
            int rr = r + h * 8;
            if (rr < M) {
                float gv0 = cg[mf][nf][2 * h],     gv1 = cg[mf][nf][2 * h + 1];
                float uv0 = cu[mf][nf][2 * h],     uv1 = cu[mf][nf][2 * h + 1];
                float h0 = gv0 / (1.f + expf(-gv0)) * uv0;
                float h1 = gv1 / (1.f + expf(-gv1)) * uv1;
                size_t o = (size_t)(base + rr) * Nn + c;
                *(__half2*)(hbuf + o) =
                    __halves2half2(__float2half_rn(h0), __float2half_rn(h1));
            }
        }
    }
}

// ---------------------------------------------------------------------------
// Down projection GEMM. BM=128 BN=128 BK=32, 512 threads, 3-stage pipeline.
// Stage: A 0, B 10240; stage stride 20480.
// ---------------------------------------------------------------------------
#define STG_DN 20480
template<bool ROUTED>
__global__ void __launch_bounds__(512)
down_mma(const fp16* __restrict__ hbuf, float* __restrict__ out, int Kk) {
    int e    = ROUTED ? blockIdx.z : 0;
    int M    = ROUTED ? g_counts[e] : N_;
    int base = ROUTED ? g_offsets[e] : 0;
    int m0 = blockIdx.x * 128;
    if (m0 >= M) return;
    int n0 = blockIdx.y * 128;

    size_t eoff = ROUTED ? (size_t)e * D_ * H_ : 0;
    const fp16* Bw = (ROUTED ? g_wd : g_sd) + eoff;

    extern __shared__ char smem[];
    int tid = threadIdx.x;
    int row = tid >> 2;
    int kq  = (tid & 3) * 16;
    int ra = m0 + row; if (ra > M - 1) ra = M - 1;
    const char* pA = (const char*)(hbuf + (size_t)(base + ra) * Kk) + kq;
    const char* pB = (const char*)(Bw + (size_t)(n0 + row) * Kk) + kq;

    uint32_t sb = (uint32_t)__cvta_generic_to_shared(smem);
    uint32_t dr = sb + row * 80 + kq;

    auto issue = [&](int stage, int kt) {
        uint32_t so = stage * STG_DN;
        size_t ko = (size_t)kt * 64;
        cpa(dr + so,         pA + ko);
        cpa(dr + so + 10240, pB + ko);
        asm volatile("cp.async.commit_group;");
    };

    int lane = tid & 31, wid = tid >> 5;
    int wm = (wid & 3) * 32;
    int wn = (wid >> 2) * 32;
    int grp = lane >> 3, lr = lane & 7;
    uint32_t aoff[2], boff[2];
#pragma unroll
    for (int mf = 0; mf < 2; mf++)
        aoff[mf] = (uint32_t)((wm + mf * 16 + (grp & 1) * 8 + lr) * 80 + (grp >> 1) * 16);
#pragma unroll
    for (int nf2 = 0; nf2 < 2; nf2++)
        boff[nf2] = (uint32_t)((wn + nf2 * 16 + (grp >> 1) * 8 + lr) * 80 + (grp & 1) * 16);

    float cd[2][4][4];
#pragma unroll
    for (int a = 0; a < 2; a++)
#pragma unroll
    for (int b = 0; b < 4; b++)
#pragma unroll
    for (int c = 0; c < 4; c++) cd[a][b][c] = 0.f;

    const int KI = Kk / 32;
    issue(0, 0);
    issue(1, 1);
    int cur = 0;
    for (int kt = 0; kt < KI; kt++) {
        if (kt + 1 < KI) {
            asm volatile("cp.async.wait_group 1;");
        } else {
            asm volatile("cp.async.wait_group 0;");
        }
        __syncthreads();
        if (kt + 2 < KI) {
            int nstage = cur + 2; if (nstage >= 3) nstage -= 3;
            issue(nstage, kt + 2);
        }
        uint32_t st = sb + cur * STG_DN;
#pragma unroll
        for (int ks = 0; ks < 2; ks++) {
            uint32_t kb = ks * 32;
            uint32_t ah[2][4], bw[2][4];
#pragma unroll
            for (int mf = 0; mf < 2; mf++)
                ldmx4(ah[mf], st + aoff[mf] + kb);
#pragma unroll
            for (int nf2 = 0; nf2 < 2; nf2++)
                ldmx4(bw[nf2], st + 10240 + boff[nf2] + kb);
#pragma unroll
            for (int mf = 0; mf < 2; mf++)
#pragma unroll
            for (int nf2 = 0; nf2 < 2; nf2++)
#pragma unroll
            for (int j = 0; j < 2; j++) {
                int nf = nf2 * 2 + j;
                mma16816(cd[mf][nf], ah[mf], &bw[nf2][2 * j]);
            }
        }
        if (++cur == 3) cur = 0;
    }

#pragma unroll
    for (int mf = 0; mf < 2; mf++)
#pragma unroll
    for (int nf = 0; nf < 4; nf++) {
        int r = m0 + wm + mf * 16 + (lane >> 2);
        int c = n0 + wn + nf * 8 + (lane & 3) * 2;
#pragma unroll
        for (int h = 0; h < 2; h++) {
            int rr = r + h * 8;
            if (rr < M) {
                float v0 = cd[mf][nf][2 * h], v1 = cd[mf][nf][2 * h + 1];
                if (ROUTED) {
                    int p = base + rr;
                    float gt = g_pgate[p];
                    float* op = out + (size_t)g_perm[p] * D_ + c;
                    atomicAdd(op,     v0 * gt);
                    atomicAdd(op + 1, v1 * gt);
                } else {
                    *(float2*)(out + (size_t)rr * D_ + c) = make_float2(v0, v1);
                }
            }
        }
    }
}

// ---------------------------------------------------------------------------
extern "C" void kernel_launch(void* const* d_in, const int* in_sizes, int n_in,
                              void* d_out, int out_size) {
    const float* x  = (const float*)d_in[0];
    const float* rw = (const float*)d_in[1];
    const float* wg = (const float*)d_in[2];
    const float* wu = (const float*)d_in[3];
    const float* wd = (const float*)d_in[4];
    const float* sg = (const float*)d_in[5];
    const float* su = (const float*)d_in[6];
    const float* sd = (const float*)d_in[7];
    float* out = (float*)d_out;

    const int SMEM_GU = 3 * STG_GU;   // 92160
    const int SMEM_DN = 3 * STG_DN;   // 61440
    cudaFuncSetAttribute(gateup_mma<false>, cudaFuncAttributeMaxDynamicSharedMemorySize, SMEM_GU);
    cudaFuncSetAttribute(gateup_mma<true>,  cudaFuncAttributeMaxDynamicSharedMemorySize, SMEM_GU);
    cudaFuncSetAttribute(down_mma<false>,   cudaFuncAttributeMaxDynamicSharedMemorySize, SMEM_DN);
    cudaFuncSetAttribute(down_mma<true>,    cudaFuncAttributeMaxDynamicSharedMemorySize, SMEM_DN);

    fp16 *pwg, *pwu, *pwd, *psg, *psu, *psd, *phs, *phr;
    cudaGetSymbolAddress((void**)&pwg, g_wg);
    cudaGetSymbolAddress((void**)&pwu, g_wu);
    cudaGetSymbolAddress((void**)&pwd, g_wd);
    cudaGetSymbolAddress((void**)&psg, g_sg);
    cudaGetSymbolAddress((void**)&psu, g_su);
    cudaGetSymbolAddress((void**)&psd, g_sd);
    cudaGetSymbolAddress((void**)&phs, g_hs);
    cudaGetSymbolAddress((void**)&phr, g_hr);

    // Fork-join capture: legacy stream = shared-expert chain,
    // s1 = router + routed chain. (Streams/events leak — only ~2 calls.)
    cudaStream_t s1;
    cudaStreamCreateWithFlags(&s1, cudaStreamNonBlocking);
    cudaEvent_t eF, eX, eS, eJ;
    cudaEventCreateWithFlags(&eF, cudaEventDisableTiming);
    cudaEventCreateWithFlags(&eX, cudaEventDisableTiming);
    cudaEventCreateWithFlags(&eS, cudaEventDisableTiming);
    cudaEventCreateWithFlags(&eJ, cudaEventDisableTiming);

    dim3 tb(32, 8);

    // Fork s1 from the capture-origin (legacy) stream.
    cudaEventRecord(eF, 0);
    cudaStreamWaitEvent(s1, eF, 0);

    // ---- legacy: shared-expert chain ----
    xconv<<<(N_ * D_ / 4) / 256, 256>>>(x);
    cudaEventRecord(eX, 0);                                  // g_x ready
    tconvh<<<dim3(HS_ / 32, D_ / 64, 1), tb>>>(sg, psg, D_, HS_);
    tconvh<<<dim3(HS_ / 32, D_ / 64, 1), tb>>>(su, psu, D_, HS_);
    gateup_mma<false><<<dim3(N_ / 128, HS_ / 128, 1), 512, SMEM_GU>>>(phs, HS_);
    tconvh<<<dim3(D_ / 32, HS_ / 64, 1), tb>>>(sd, psd, HS_, D_);
    down_mma<false><<<dim3(N_ / 128, D_ / 128, 1), 512, SMEM_DN>>>(phs, out, HS_);
    cudaEventRecord(eS, 0);                                  // out initialized

    // ---- s1: router + routed chain ----
    router_kernel<<<N_ / 8, 256, 0, s1>>>(x, rw);
    build_lists_kernel<<<1, 256, 0, s1>>>();
    tconvh<<<dim3(H_ / 32, D_ / 64, E_), tb, 0, s1>>>(wg, pwg, D_, H_);
    tconvh<<<dim3(H_ / 32, D_ / 64, E_), tb, 0, s1>>>(wu, pwu, D_, H_);
    cudaStreamWaitEvent(s1, eX, 0);                          // need g_x
    gateup_mma<true><<<dim3(N_ / 128, H_ / 128, E_), 512, SMEM_GU, s1>>>(phr, H_);
    tconvh<<<dim3(D_ / 32, H_ / 64, E_), tb, 0, s1>>>(wd, pwd, H_, D_);
    cudaStreamWaitEvent(s1, eS, 0);                          // need out init
    down_mma<true><<<dim3(N_ / 128, D_ / 128, E_), 512, SMEM_DN, s1>>>(phr, out, H_);
    cudaEventRecord(eJ, s1);

    // join back to legacy stream
    cudaStreamWaitEvent(0, eJ, 0);
}

// round 12
// speedup vs baseline: 6.6389x; 1.0168x over previous
#include <cuda_runtime.h>
#include <cuda_fp16.h>
#include <cstdint>

#define D_  2048
#define H_  1408
#define HS_ 2816
#define E_  8
#define N_  4096
#define NK_ (2*N_)

typedef __half fp16;

constexpr size_t EDH = (size_t)E_ * D_ * H_;
constexpr size_t DHS = (size_t)D_ * HS_;
constexpr size_t XSZ = (size_t)N_ * D_;

// -------- static scratch (no runtime allocation allowed) --------
__device__ fp16 g_wg[EDH];            // transposed [E][H][D]
__device__ fp16 g_wu[EDH];
__device__ fp16 g_wd[EDH];            // transposed [E][D][H]
__device__ fp16 g_sg[DHS];            // transposed [HS][D]
__device__ fp16 g_su[DHS];
__device__ fp16 g_sd[DHS];            // transposed [D][HS]
__device__ fp16 g_x[XSZ];             // [N][D]
__device__ fp16 g_hs[(size_t)N_ * HS_];    // shared-expert hidden
__device__ fp16 g_hr[(size_t)NK_ * H_];    // routed hidden
__device__ int   g_perm[NK_];
__device__ float g_pgate[NK_];
__device__ int   g_counts[E_];
__device__ int   g_offsets[E_ + 1];
__device__ int   g_gidx[NK_];
__device__ float g_gval[NK_];

// -------- helpers --------
__device__ __forceinline__ void cpa(uint32_t d, const void* s) {
    asm volatile("cp.async.cg.shared.global [%0], [%1], 16;" :: "r"(d), "l"(s));
}
__device__ __forceinline__ void ldmx4(uint32_t* r, uint32_t a) {
    asm volatile("ldmatrix.sync.aligned.m8n8.x4.shared.b16 {%0,%1,%2,%3}, [%4];"
                 : "=r"(r[0]), "=r"(r[1]), "=r"(r[2]), "=r"(r[3]) : "r"(a));
}
__device__ __forceinline__ void mma16816(float* c, const uint32_t* a, const uint32_t* b) {
    asm volatile(
        "mma.sync.aligned.m16n8k16.row.col.f32.f16.f16.f32 "
        "{%0,%1,%2,%3},{%4,%5,%6,%7},{%8,%9},{%0,%1,%2,%3};"
        : "+f"(c[0]), "+f"(c[1]), "+f"(c[2]), "+f"(c[3])
        : "r"(a[0]), "r"(a[1]), "r"(a[2]), "r"(a[3]), "r"(b[0]), "r"(b[1]));
}

// -------- conversion kernels --------
__global__ void tconvh(const float* __restrict__ src, fp16* __restrict__ dst,
                       int R, int C) {
    __shared__ float t[64][33];
    size_t zo = (size_t)blockIdx.z * R * C;
    src += zo; dst += zo;
    int c0 = blockIdx.x * 32, r0 = blockIdx.y * 64;
    int tx = threadIdx.x, ty = threadIdx.y;
#pragma unroll
    for (int i = 0; i < 8; i++)
        t[ty + 8 * i][tx] = src[(size_t)(r0 + ty + 8 * i) * C + c0 + tx];
    __syncthreads();
#pragma unroll
    for (int i = 0; i < 4; i++) {
        int cx = ty + 8 * i;
        float v0 = t[2 * tx][cx];
        float v1 = t[2 * tx + 1][cx];
        *(__half2*)(dst + (size_t)(c0 + cx) * R + r0 + 2 * tx) =
            __halves2half2(__float2half_rn(v0), __float2half_rn(v1));
    }
}

__global__ void xconv(const float* __restrict__ x) {
    size_t i = (size_t)blockIdx.x * blockDim.x + threadIdx.x;
    float4 v = ((const float4*)x)[i];
    __half2* p = (__half2*)(g_x + 4 * i);
    p[0] = __halves2half2(__float2half_rn(v.x), __float2half_rn(v.y));
    p[1] = __halves2half2(__float2half_rn(v.z), __float2half_rn(v.w));
}

// -------- router + list build (proven) --------
__global__ void router_kernel(const float* __restrict__ x, const float* __restrict__ rw) {
    int gw = (blockIdx.x * blockDim.x + threadIdx.x) >> 5;
    int lane = threadIdx.x & 31;
    if (gw >= N_) return;
    const float* xr = x + (size_t)gw * D_;
    float acc[E_];
#pragma unroll
    for (int e = 0; e < E_; e++) acc[e] = 0.f;
    for (int d = lane * 4; d < D_; d += 128) {
        float4 xv = *(const float4*)(xr + d);
#pragma unroll
        for (int e = 0; e < E_; e++) {
            float4 wv = *(const float4*)(rw + e * D_ + d);
            acc[e] += xv.x * wv.x + xv.y * wv.y + xv.z * wv.z + xv.w * wv.w;
        }
    }
#pragma unroll
    for (int e = 0; e < E_; e++) {
#pragma unroll
        for (int o = 16; o > 0; o >>= 1)
            acc[e] += __shfl_down_sync(0xffffffffu, acc[e], o);
    }
    if (lane == 0) {
        float mx = acc[0];
#pragma unroll
        for (int e = 1; e < E_; e++) mx = fmaxf(mx, acc[e]);
        float p[E_], s = 0.f;
#pragma unroll
        for (int e = 0; e < E_; e++) { p[e] = expf(acc[e] - mx); s += p[e]; }
        int i1 = 0;
#pragma unroll
        for (int e = 1; e < E_; e++) if (p[e] > p[i1]) i1 = e;
        int i2 = (i1 == 0) ? 1 : 0;
#pragma unroll
        for (int e = 0; e < E_; e++) if (e != i1 && p[e] > p[i2]) i2 = e;
        float g1 = p[i1] / s, g2 = p[i2] / s;
        float den = g1 + g2 + 1e-20f;
        g_gidx[2 * gw]     = i1; g_gval[2 * gw]     = g1 / den;
        g_gidx[2 * gw + 1] = i2; g_gval[2 * gw + 1] = g2 / den;
    }
}

__global__ void build_lists_kernel() {
    __shared__ int scnt[E_];
    __shared__ int soff[E_];
    int wid = threadIdx.x >> 5, lane = threadIdx.x & 31;
    if (wid < E_) {
        int c = 0;
        for (int base = 0; base < NK_; base += 32) {
            int flag = (g_gidx[base + lane] == wid);
            c += __popc(__ballot_sync(0xffffffffu, flag));
        }
        if (lane == 0) scnt[wid] = c;
    }
    __syncthreads();
    if (threadIdx.x == 0) {
        int s = 0;
        for (int e = 0; e < E_; e++) {
            soff[e] = s; g_offsets[e] = s; g_counts[e] = scnt[e]; s += scnt[e];
        }
        g_offsets[E_] = s;
    }
    __syncthreads();
    if (wid < E_) {
        int pos = soff[wid];
        for (int base = 0; base < NK_; base += 32) {
            int t = base + lane;
            int flag = (g_gidx[t] == wid);
            unsigned m = __ballot_sync(0xffffffffu, flag);
            if (flag) {
                int off = __popc(m & ((1u << lane) - 1u));
                g_perm[pos + off]  = t >> 1;
                g_pgate[pos + off] = g_gval[t];
            }
            pos += __popc(m);
        }
    }
}

// ---------------------------------------------------------------------------
// Fused gate/up GEMM + SiLU -> hbuf. BM=128 BN=128 BK=64, 512 threads
// (16 warps, 4m x 4n, warp tile 32x32), fp16 x fp16 -> fp32.
// 3-stage cp.async pipeline, one sync per iter; B fragments double-buffered
// one k-step ahead so LDSM overlaps HMMA.
// Rows 144B (128B data + 16B pad). Tile 128*144 = 18432B.
// Stage: A 0, G 18432, U 36864. Stage stride 55296.
// ---------------------------------------------------------------------------
#define STG_GU 55296
template<bool ROUTED>
__global__ void __launch_bounds__(512)
gateup_mma(fp16* __restrict__ hbuf, int Nn) {
    int e    = ROUTED ? blockIdx.z : 0;
    int M    = ROUTED ? g_counts[e] : N_;
    int base = ROUTED ? g_offsets[e] : 0;
    int m0 = blockIdx.x * 128;
    if (m0 >= M) return;
    int n0 = blockIdx.y * 128;

    size_t eoff = ROUTED ? (size_t)e * D_ * H_ : 0;
    const fp16* Bg = (ROUTED ? g_wg : g_sg) + eoff;
    const fp16* Bu = (ROUTED ? g_wu : g_su) + eoff;

    extern __shared__ char smem[];
    __shared__ int stok[128];
    int tid = threadIdx.x;
    if (tid < 128) {
        int r = m0 + tid; if (r > M - 1) r = M - 1;
        stok[tid] = ROUTED ? g_perm[base + r] : r;
    }
    __syncthreads();

    int row = tid >> 2;           // 0..127
    int kq  = (tid & 3) * 16;     // first 16B chunk within 128B row
    const char* pA = (const char*)(g_x + (size_t)stok[row] * D_) + kq;
    const char* pG = (const char*)(Bg + (size_t)(n0 + row) * D_) + kq;
    const char* pU = (const char*)(Bu + (size_t)(n0 + row) * D_) + kq;

    uint32_t sb = (uint32_t)__cvta_generic_to_shared(smem);
    uint32_t dr = sb + row * 144 + kq;

    auto issue = [&](int stage, int kt) {
        uint32_t so = stage * STG_GU;
        size_t ko = (size_t)kt * 128;
        cpa(dr + so,              pA + ko);
        cpa(dr + so + 64,         pA + ko + 64);
        cpa(dr + so + 18432,      pG + ko);
        cpa(dr + so + 18432 + 64, pG + ko + 64);
        cpa(dr + so + 36864,      pU + ko);
        cpa(dr + so + 36864 + 64, pU + ko + 64);
        asm volatile("cp.async.commit_group;");
    };

    int lane = tid & 31, wid = tid >> 5;
    int wm = (wid & 3) * 32;
    int wn = (wid >> 2) * 32;
    int grp = lane >> 3, lr = lane & 7;
    uint32_t aoff[2], boff[2];
#pragma unroll
    for (int mf = 0; mf < 2; mf++)
        aoff[mf] = (uint32_t)((wm + mf * 16 + (grp & 1) * 8 + lr) * 144 + (grp >> 1) * 16);
#pragma unroll
    for (int nf2 = 0; nf2 < 2; nf2++)
        boff[nf2] = (uint32_t)((wn + nf2 * 16 + (grp >> 1) * 8 + lr) * 144 + (grp & 1) * 16);

    float cg[2][4][4], cu[2][4][4];
#pragma unroll
    for (int a = 0; a < 2; a++)
#pragma unroll
    for (int b = 0; b < 4; b++)
#pragma unroll
    for (int c = 0; c < 4; c++) { cg[a][b][c] = 0.f; cu[a][b][c] = 0.f; }

    const int KI = D_ / 64;   // 32
    issue(0, 0);
    issue(1, 1);
    int cur = 0;
    for (int kt = 0; kt < KI; kt++) {
        if (kt + 1 < KI) {
            asm volatile("cp.async.wait_group 1;");
        } else {
            asm volatile("cp.async.wait_group 0;");
        }
        __syncthreads();
        if (kt + 2 < KI) {
            int nstage = cur + 2; if (nstage >= 3) nstage -= 3;
            issue(nstage, kt + 2);
        }
        uint32_t st = sb + cur * STG_GU;

        uint32_t bgf[2][2][4], buf_[2][2][4];
#pragma unroll
        for (int nf2 = 0; nf2 < 2; nf2++) {
            ldmx4(bgf[0][nf2], st + 18432 + boff[nf2]);
            ldmx4(buf_[0][nf2], st + 36864 + boff[nf2]);
        }
#pragma unroll
        for (int ks = 0; ks < 4; ks++) {
            int cb = ks & 1;
            if (ks < 3) {
                uint32_t kb = (ks + 1) * 32;
#pragma unroll
                for (int nf2 = 0; nf2 < 2; nf2++) {
                    ldmx4(bgf[cb ^ 1][nf2], st + 18432 + boff[nf2] + kb);
                    ldmx4(buf_[cb ^ 1][nf2], st + 36864 + boff[nf2] + kb);
                }
            }
            uint32_t ah[2][4];
            uint32_t kb = ks * 32;
#pragma unroll
            for (int mf = 0; mf < 2; mf++)
                ldmx4(ah[mf], st + aoff[mf] + kb);
#pragma unroll
            for (int mf = 0; mf < 2; mf++)
#pragma unroll
            for (int nf2 = 0; nf2 < 2; nf2++)
#pragma unroll
            for (int j = 0; j < 2; j++) {
                int nf = nf2 * 2 + j;
                mma16816(cg[mf][nf], ah[mf], &bgf[cb][nf2][2 * j]);
                mma16816(cu[mf][nf], ah[mf], &buf_[cb][nf2][2 * j]);
            }
        }
        if (++cur == 3) cur = 0;
    }

#pragma unroll
    for (int mf = 0; mf < 2; mf++)
#pragma unroll
    for (int nf = 0; nf < 4; nf++) {
        int r = m0 + wm + mf * 16 + (lane >> 2);
        int c = n0 + wn + nf * 8 + (lane & 3) * 2;
#pragma unroll
        for (int h = 0; h < 2; h++) {
            int rr = r + h * 8;
            if (rr < M) {
                float gv0 = cg[mf][nf][2 * h],     gv1 = cg[mf][nf][2 * h + 1];
                float uv0 = cu[mf][nf][2 * h],     uv1 = cu[mf][nf][2 * h + 1];
                float h0 = gv0 / (1.f + expf(-gv0)) * uv0;
                float h1 = gv1 / (1.f + expf(-gv1)) * uv1;
                size_t o = (size_t)(base + rr) * Nn + c;
                *(__half2*)(hbuf + o) =
                    __halves2half2(__float2half_rn(h0), __float2half_rn(h1));
            }
        }
    }
}

// ---------------------------------------------------------------------------
// Down projection GEMM. BM=128 BN=128 BK=64, 512 threads, 3-stage pipeline,
// B fragments double-buffered. Rows 144B. Stage: A 0, B 18432; stride 36864.
// ---------------------------------------------------------------------------
#define STG_DN 36864
template<bool ROUTED>
__global__ void __launch_bounds__(512)
down_mma(const fp16* __restrict__ hbuf, float* __restrict__ out, int Kk) {
    int e    = ROUTED ? blockIdx.z : 0;
    int M    = ROUTED ? g_counts[e] : N_;
    int base = ROUTED ? g_offsets[e] : 0;
    int m0 = blockIdx.x * 128;
    if (m0 >= M) return;
    int n0 = blockIdx.y * 128;

    size_t eoff = ROUTED ? (size_t)e * D_ * H_ : 0;
    const fp16* Bw = (ROUTED ? g_wd : g_sd) + eoff;

    extern __shared__ char smem[];
    int tid = threadIdx.x;
    int row = tid >> 2;
    int kq  = (tid & 3) * 16;
    int ra = m0 + row; if (ra > M - 1) ra = M - 1;
    const char* pA = (const char*)(hbuf + (size_t)(base + ra) * Kk) + kq;
    const char* pB = (const char*)(Bw + (size_t)(n0 + row) * Kk) + kq;

    uint32_t sb = (uint32_t)__cvta_generic_to_shared(smem);
    uint32_t dr = sb + row * 144 + kq;

    auto issue = [&](int stage, int kt) {
        uint32_t so = stage * STG_DN;
        size_t ko = (size_t)kt * 128;
        cpa(dr + so,              pA + ko);
        cpa(dr + so + 64,         pA + ko + 64);
        cpa(dr + so + 18432,      pB + ko);
        cpa(dr + so + 18432 + 64, pB + ko + 64);
        asm volatile("cp.async.commit_group;");
    };

    int lane = tid & 31, wid = tid >> 5;
    int wm = (wid & 3) * 32;
    int wn = (wid >> 2) * 32;
    int grp = lane >> 3, lr = lane & 7;
    uint32_t aoff[2], boff[2];
#pragma unroll
    for (int mf = 0; mf < 2; mf++)
        aoff[mf] = (uint32_t)((wm + mf * 16 + (grp & 1) * 8 + lr) * 144 + (grp >> 1) * 16);
#pragma unroll
    for (int nf2 = 0; nf2 < 2; nf2++)
        boff[nf2] = (uint32_t)((wn + nf2 * 16 + (grp >> 1) * 8 + lr) * 144 + (grp & 1) * 16);

    float cd[2][4][4];
#pragma unroll
    for (int a = 0; a < 2; a++)
#pragma unroll
    for (int b = 0; b < 4; b++)
#pragma unroll
    for (int c = 0; c < 4; c++) cd[a][b][c] = 0.f;

    const int KI = Kk / 64;
    issue(0, 0);
    issue(1, 1);
    int cur = 0;
    for (int kt = 0; kt < KI; kt++) {
        if (kt + 1 < KI) {
            asm volatile("cp.async.wait_group 1;");
        } else {
            asm volatile("cp.async.wait_group 0;");
        }
        __syncthreads();
        if (kt + 2 < KI) {
            int nstage = cur + 2; if (nstage >= 3) nstage -= 3;
            issue(nstage, kt + 2);
        }
        uint32_t st = sb + cur * STG_DN;

        uint32_t bwf[2][2][4];
#pragma unroll
        for (int nf2 = 0; nf2 < 2; nf2++)
            ldmx4(bwf[0][nf2], st + 18432 + boff[nf2]);
#pragma unroll
        for (int ks = 0; ks < 4; ks++) {
            int cb = ks & 1;
            if (ks < 3) {
                uint32_t kb = (ks + 1) * 32;
#pragma unroll
                for (int nf2 = 0; nf2 < 2; nf2++)
                    ldmx4(bwf[cb ^ 1][nf2], st + 18432 + boff[nf2] + kb);
            }
            uint32_t ah[2][4];
            uint32_t kb = ks * 32;
#pragma unroll
            for (int mf = 0; mf < 2; mf++)
                ldmx4(ah[mf], st + aoff[mf] + kb);
#pragma unroll
            for (int mf = 0; mf < 2; mf++)
#pragma unroll
            for (int nf2 = 0; nf2 < 2; nf2++)
#pragma unroll
            for (int j = 0; j < 2; j++) {
                int nf = nf2 * 2 + j;
                mma16816(cd[mf][nf], ah[mf], &bwf[cb][nf2][2 * j]);
            }
        }
        if (++cur == 3) cur = 0;
    }

#pragma unroll
    for (int mf = 0; mf < 2; mf++)
#pragma unroll
    for (int nf = 0; nf < 4; nf++) {
        int r = m0 + wm + mf * 16 + (lane >> 2);
        int c = n0 + wn + nf * 8 + (lane & 3) * 2;
#pragma unroll
        for (int h = 0; h < 2; h++) {
            int rr = r + h * 8;
            if (rr < M) {
                float v0 = cd[mf][nf][2 * h], v1 = cd[mf][nf][2 * h + 1];
                if (ROUTED) {
                    int p = base + rr;
                    float gt = g_pgate[p];
                    float* op = out + (size_t)g_perm[p] * D_ + c;
                    atomicAdd(op,     v0 * gt);
                    atomicAdd(op + 1, v1 * gt);
                } else {
                    *(float2*)(out + (size_t)rr * D_ + c) = make_float2(v0, v1);
                }
            }
        }
    }
}

// ---------------------------------------------------------------------------
extern "C" void kernel_launch(void* const* d_in, const int* in_sizes, int n_in,
                              void* d_out, int out_size) {
    const float* x  = (const float*)d_in[0];
    const float* rw = (const float*)d_in[1];
    const float* wg = (const float*)d_in[2];
    const float* wu = (const float*)d_in[3];
    const float* wd = (const float*)d_in[4];
    const float* sg = (const float*)d_in[5];
    const float* su = (const float*)d_in[6];
    const float* sd = (const float*)d_in[7];
    float* out = (float*)d_out;

    const int SMEM_GU = 3 * STG_GU;   // 165888
    const int SMEM_DN = 3 * STG_DN;   // 110592
    cudaFuncSetAttribute(gateup_mma<false>, cudaFuncAttributeMaxDynamicSharedMemorySize, SMEM_GU);
    cudaFuncSetAttribute(gateup_mma<true>,  cudaFuncAttributeMaxDynamicSharedMemorySize, SMEM_GU);
    cudaFuncSetAttribute(down_mma<false>,   cudaFuncAttributeMaxDynamicSharedMemorySize, SMEM_DN);
    cudaFuncSetAttribute(down_mma<true>,    cudaFuncAttributeMaxDynamicSharedMemorySize, SMEM_DN);

    fp16 *pwg, *pwu, *pwd, *psg, *psu, *psd, *phs, *phr;
    cudaGetSymbolAddress((void**)&pwg, g_wg);
    cudaGetSymbolAddress((void**)&pwu, g_wu);
    cudaGetSymbolAddress((void**)&pwd, g_wd);
    cudaGetSymbolAddress((void**)&psg, g_sg);
    cudaGetSymbolAddress((void**)&psu, g_su);
    cudaGetSymbolAddress((void**)&psd, g_sd);
    cudaGetSymbolAddress((void**)&phs, g_hs);
    cudaGetSymbolAddress((void**)&phr, g_hr);

    cudaStream_t s1;
    cudaStreamCreateWithFlags(&s1, cudaStreamNonBlocking);
    cudaEvent_t eF, eX, eS, eJ;
    cudaEventCreateWithFlags(&eF, cudaEventDisableTiming);
    cudaEventCreateWithFlags(&eX, cudaEventDisableTiming);
    cudaEventCreateWithFlags(&eS, cudaEventDisableTiming);
    cudaEventCreateWithFlags(&eJ, cudaEventDisableTiming);

    dim3 tb(32, 8);

    cudaEventRecord(eF, 0);
    cudaStreamWaitEvent(s1, eF, 0);

    // ---- legacy: shared-expert chain ----
    xconv<<<(N_ * D_ / 4) / 256, 256>>>(x);
    cudaEventRecord(eX, 0);                                  // g_x ready
    tconvh<<<dim3(HS_ / 32, D_ / 64, 1), tb>>>(sg, psg, D_, HS_);
    tconvh<<<dim3(HS_ / 32, D_ / 64, 1), tb>>>(su, psu, D_, HS_);
    gateup_mma<false><<<dim3(N_ / 128, HS_ / 128, 1), 512, SMEM_GU>>>(phs, HS_);
    tconvh<<<dim3(D_ / 32, HS_ / 64, 1), tb>>>(sd, psd, HS_, D_);
    down_mma<false><<<dim3(N_ / 128, D_ / 128, 1), 512, SMEM_DN>>>(phs, out, HS_);
    cudaEventRecord(eS, 0);                                  // out initialized

    // ---- s1: router + routed chain ----
    router_kernel<<<N_ / 8, 256, 0, s1>>>(x, rw);
    build_lists_kernel<<<1, 256, 0, s1>>>();
    tconvh<<<dim3(H_ / 32, D_ / 64, E_), tb, 0, s1>>>(wg, pwg, D_, H_);
    tconvh<<<dim3(H_ / 32, D_ / 64, E_), tb, 0, s1>>>(wu, pwu, D_, H_);
    cudaStreamWaitEvent(s1, eX, 0);                          // need g_x
    gateup_mma<true><<<dim3(N_ / 128, H_ / 128, E_), 512, SMEM_GU, s1>>>(phr, H_);
    tconvh<<<dim3(D_ / 32, H_ / 64, E_), tb, 0, s1>>>(wd, pwd, H_, D_);
    cudaStreamWaitEvent(s1, eS, 0);                          // need out init
    down_mma<true><<<dim3(N_ / 128, D_ / 128, E_), 512, SMEM_DN, s1>>>(phr, out, H_);
    cudaEventRecord(eJ, s1);

    cudaStreamWaitEvent(0, eJ, 0);
}